// round 9
// baseline (speedup 1.0000x reference)
#include <cuda_runtime.h>
#include <cuda_fp16.h>
#include <cstdint>
#include <math_constants.h>

#define NN 8192
#define DD 512

static __device__ __forceinline__ float INVEPS() { return 1.0f / 0.05f; }
#define KLOG (-9.010913347279288f)   /* -ln(8192) */

// ---------------- static device scratch (no cudaMalloc allowed) -------------------
__device__ float  g_Czx[8192ull * 8192ull];   // fp32 dist(prior_z, x)   (extrapolation)
__device__ float  g_Czz[8192ull * 8192ull];   // fp32 dist(z, z)
__device__ float  g_Cxx[8192ull * 8192ull];   // fp32 dist(x, x)
__device__ __half g_Hzx[8192ull * 8192ull];   // fp16 copies (iteration loop)
__device__ __half g_Hzz[8192ull * 8192ull];
__device__ __half g_Hxx[8192ull * 8192ull];
__device__ float  g_Zr[NN * DD];              // tf32-rounded prior_z
__device__ float  g_Xr[NN * DD];              // tf32-rounded x
__device__ float  g_nz[NN];                   // |z_i|^2 (fp32, original inputs)
__device__ float  g_nx[NN];
__device__ float  g_vecbuf[2 * 4 * NN];       // [buf][f,g,p,q][NN]
__device__ float  g_partM[32ull * NN];        // column-lse partial maxes
__device__ float  g_partS[32ull * NN];        // column-lse partial sums

// ---------------- setup kernels ----------------------------------------------------

__global__ void __launch_bounds__(256) preround_kernel(const float* __restrict__ in,
                                                       float* __restrict__ out) {
    int i = blockIdx.x * 256 + threadIdx.x;
    if (i < NN * DD) {
        float v = in[i];
        uint32_t u;
        asm("cvt.rna.tf32.f32 %0, %1;" : "=r"(u) : "f"(v));
        out[i] = __uint_as_float(u);
    }
}

// Row squared norms in fp32 on ORIGINAL inputs (reference: jnp.sum(x*x, -1)).
__global__ void __launch_bounds__(128) sqnorm_kernel(const float* __restrict__ X,
                                                     float* __restrict__ out) {
    __shared__ float sm[128];
    int r = blockIdx.x;
    const float4* row = (const float4*)(X + (size_t)r * DD);
    float4 v = row[threadIdx.x];
    float s = v.x * v.x + v.y * v.y + v.z * v.z + v.w * v.w;
    sm[threadIdx.x] = s;
    __syncthreads();
    for (int o = 64; o > 0; o >>= 1) {
        if (threadIdx.x < o) sm[threadIdx.x] += sm[threadIdx.x + o];
        __syncthreads();
    }
    if (threadIdx.x == 0) out[r] = sm[0];
}

// ---------------- TF32 tensor-core distance GEMM (dual fp32+fp16 output) ----------

#define SWZ(m, k) (((m) * 32) + ((k) ^ (((m) & 7) << 2)))

#define MMA_TF32(d, a, b0, b1)                                               \
    asm volatile(                                                            \
        "mma.sync.aligned.m16n8k8.row.col.f32.tf32.tf32.f32 "                \
        "{%0,%1,%2,%3},{%4,%5,%6,%7},{%8,%9},{%0,%1,%2,%3};"                 \
        : "+f"((d)[0]), "+f"((d)[1]), "+f"((d)[2]), "+f"((d)[3])             \
        : "r"((a)[0]), "r"((a)[1]), "r"((a)[2]), "r"((a)[3]),                \
          "r"(b0), "r"(b1))

__device__ __forceinline__ void cp_async16(uint32_t smem_addr, const float* gptr) {
    asm volatile("cp.async.cg.shared.global [%0], [%1], 16;\n"
                 :: "r"(smem_addr), "l"(gptr));
}

__device__ __forceinline__ void gemm_issue_stage(const float* __restrict__ A,
                                                 const float* __restrict__ B,
                                                 size_t rA, size_t rB, int k0,
                                                 float* dA, int tid) {
    float* dB = dA + 4096;
#pragma unroll
    for (int j = 0; j < 4; j++) {
        int idx = tid + 256 * j;
        int m = idx >> 3;
        int kq = idx & 7;
        uint32_t off = (uint32_t)(SWZ(m, kq * 4)) * 4u;
        uint32_t sa = (uint32_t)__cvta_generic_to_shared(dA) + off;
        uint32_t sb = (uint32_t)__cvta_generic_to_shared(dB) + off;
        cp_async16(sa, A + (rA + m) * DD + k0 + kq * 4);
        cp_async16(sb, B + (rB + m) * DD + k0 + kq * 4);
    }
    asm volatile("cp.async.commit_group;\n" ::);
}

__global__ void __launch_bounds__(256, 2)
gemm_tc_kernel(const float* __restrict__ A, const float* __restrict__ B,
               const float* __restrict__ na, const float* __restrict__ nb,
               float* __restrict__ C, __half* __restrict__ H) {
    extern __shared__ float smem[];   // 2 x (4096 + 4096) floats = 64 KB
    int tid = threadIdx.x;
    int lane = tid & 31, w = tid >> 5;
    int wm = w >> 1, wn = w & 1;
    int g = lane >> 2, c = lane & 3;
    size_t rA = (size_t)blockIdx.y * 128;
    size_t rB = (size_t)blockIdx.x * 128;

    float acc[2][8][4] = {};

    gemm_issue_stage(A, B, rA, rB, 0, smem, tid);
    gemm_issue_stage(A, B, rA, rB, 32, smem + 8192, tid);

    for (int s = 0; s < 16; s++) {
        asm volatile("cp.async.wait_group 1;\n" ::);
        __syncthreads();
        {
            const float* As = smem + (s & 1) * 8192;
            const float* Bs = As + 4096;
#pragma unroll
            for (int k8 = 0; k8 < 4; k8++) {
                int kb = k8 * 8;
                uint32_t a[2][4];
#pragma unroll
                for (int mt = 0; mt < 2; mt++) {
                    int mb = wm * 32 + mt * 16;
                    a[mt][0] = __float_as_uint(As[SWZ(mb + g,     kb + c)]);
                    a[mt][1] = __float_as_uint(As[SWZ(mb + 8 + g, kb + c)]);
                    a[mt][2] = __float_as_uint(As[SWZ(mb + g,     kb + 4 + c)]);
                    a[mt][3] = __float_as_uint(As[SWZ(mb + 8 + g, kb + 4 + c)]);
                }
#pragma unroll
                for (int nt = 0; nt < 8; nt++) {
                    int nb_ = wn * 64 + nt * 8;
                    uint32_t b0 = __float_as_uint(Bs[SWZ(nb_ + g, kb + c)]);
                    uint32_t b1 = __float_as_uint(Bs[SWZ(nb_ + g, kb + 4 + c)]);
                    MMA_TF32(acc[0][nt], a[0], b0, b1);
                    MMA_TF32(acc[1][nt], a[1], b0, b1);
                }
            }
        }
        __syncthreads();
        if (s + 2 < 16)
            gemm_issue_stage(A, B, rA, rB, (s + 2) * 32, smem + ((s & 1) * 8192), tid);
        else
            asm volatile("cp.async.commit_group;\n" ::);
    }

    // epilogue: o = sqrt(max(na + nb - 2*acc, 1e-12)); write fp32 + fp16
#pragma unroll
    for (int mt = 0; mt < 2; mt++) {
        size_t m0 = rA + wm * 32 + mt * 16 + g;
        float na0 = __ldg(na + m0);
        float na1 = __ldg(na + m0 + 8);
#pragma unroll
        for (int nt = 0; nt < 8; nt++) {
            size_t n0 = rB + wn * 64 + nt * 8 + 2 * c;
            float nb0 = __ldg(nb + n0);
            float nb1 = __ldg(nb + n0 + 1);
            float2 o;
            o.x = sqrtf(fmaxf(na0 + nb0 - 2.0f * acc[mt][nt][0], 1e-12f));
            o.y = sqrtf(fmaxf(na0 + nb1 - 2.0f * acc[mt][nt][1], 1e-12f));
            __stcs((float2*)(C + m0 * NN + n0), o);
            *(__half2*)(H + m0 * NN + n0) = __float22half2_rn(o);
            o.x = sqrtf(fmaxf(na1 + nb0 - 2.0f * acc[mt][nt][2], 1e-12f));
            o.y = sqrtf(fmaxf(na1 + nb1 - 2.0f * acc[mt][nt][3], 1e-12f));
            __stcs((float2*)(C + (m0 + 8) * NN + n0), o);
            *(__half2*)(H + (m0 + 8) * NN + n0) = __float22half2_rn(o);
        }
    }
}

// fp32 diagonal fix for self-distance matrices (different reduction order than
// sqnorm -> reproduces reference's independent-roundoff cancellation stats).
__global__ void __launch_bounds__(256)
diag_fix_kernel(const float* __restrict__ X, const float* __restrict__ n,
                float* __restrict__ C, __half* __restrict__ H) {
    int row = blockIdx.x * 8 + (threadIdx.x >> 5);
    int l = threadIdx.x & 31;
    const float* xr = X + (size_t)row * DD;
    float s = 0.0f;
#pragma unroll
    for (int k = 0; k < DD / 32; k++) {
        float v = xr[l + k * 32];
        s = fmaf(v, v, s);
    }
#pragma unroll
    for (int o = 16; o > 0; o >>= 1)
        s += __shfl_xor_sync(0xFFFFFFFFu, s, o);
    if (l == 0) {
        float d = sqrtf(fmaxf(2.0f * n[row] - 2.0f * s, 1e-12f));
        C[(size_t)row * NN + row] = d;
        H[(size_t)row * NN + row] = __float2half_rn(d);
    }
}

// ---------------- iteration-loop lse kernels (fp16 costs) --------------------------

__global__ void __launch_bounds__(256) zero_kernel(float* __restrict__ p, int n) {
    int i = blockIdx.x * 256 + threadIdx.x;
    if (i < n) p[i] = 0.0f;
}

#define LSE_STEP(a) do { \
    if ((a) <= m) s += __expf((a) - m); \
    else { s = s * __expf(m - (a)) + 1.0f; m = (a); } } while (0)

// uout[i] = cu*uold[i] + cl*( lse_j((v[j]-C[i][j])/eps) + KLOG ), fp16 C.
__global__ void __launch_bounds__(256)
rowlse_h_kernel(const __half* __restrict__ C, const float* __restrict__ v,
                const float* __restrict__ uold, float* __restrict__ uout,
                float cu, float cl) {
    __shared__ float vs[NN];
    __shared__ float redm[256], reds[256];
    int tid = threadIdx.x;
    for (int j = tid; j < NN; j += 256) vs[j] = v[j];
    __syncthreads();

    const uint4* Crow = (const uint4*)(C + (size_t)blockIdx.x * NN);  // 8 halves per uint4
    float m = -CUDART_INF_F, s = 0.0f;
    const float ie = INVEPS();
#pragma unroll
    for (int jj = 0; jj < 4; jj++) {
        int u = tid + jj * 256;
        uint4 raw = __ldcs(Crow + u);
        const __half2* hp = (const __half2*)&raw;
        const float* vp = &vs[u << 3];
        float2 c0 = __half22float2(hp[0]);
        float2 c1 = __half22float2(hp[1]);
        float2 c2 = __half22float2(hp[2]);
        float2 c3 = __half22float2(hp[3]);
        float a;
        a = (vp[0] - c0.x) * ie; LSE_STEP(a);
        a = (vp[1] - c0.y) * ie; LSE_STEP(a);
        a = (vp[2] - c1.x) * ie; LSE_STEP(a);
        a = (vp[3] - c1.y) * ie; LSE_STEP(a);
        a = (vp[4] - c2.x) * ie; LSE_STEP(a);
        a = (vp[5] - c2.y) * ie; LSE_STEP(a);
        a = (vp[6] - c3.x) * ie; LSE_STEP(a);
        a = (vp[7] - c3.y) * ie; LSE_STEP(a);
    }
    redm[tid] = m; reds[tid] = s;
    __syncthreads();
    for (int o = 128; o > 0; o >>= 1) {
        if (tid < o) {
            float m2 = redm[tid + o], s2 = reds[tid + o];
            float M = fmaxf(m, m2);
            s = s * __expf(m - M) + s2 * __expf(m2 - M);
            m = M;
            redm[tid] = m; reds[tid] = s;
        }
        __syncthreads();
    }
    if (tid == 0)
        uout[blockIdx.x] = cu * uold[blockIdx.x] + cl * (__logf(s) + m + KLOG);
}

// Column-lse pass 1 on fp16: block = 512 cols (half2 per thread) x 256-row chunk.
__global__ void __launch_bounds__(256)
collse_part_h_kernel(const __half* __restrict__ C, const float* __restrict__ v) {
    __shared__ float vsh[256];
    int tid = threadIdx.x;
    int col2 = blockIdx.x * 256 + tid;           // half2 index
    int r0 = blockIdx.y * 256;
    vsh[tid] = v[r0 + tid];
    __syncthreads();
    const __half2* Cp = (const __half2*)C + (size_t)r0 * (NN / 2) + col2;
    float m0 = -CUDART_INF_F, s0 = 0.0f, m1 = -CUDART_INF_F, s1 = 0.0f;
    const float ie = INVEPS();
#pragma unroll 8
    for (int r = 0; r < 256; r++) {
        float2 cc = __half22float2(__ldcs(Cp));
        Cp += NN / 2;
        float vr = vsh[r];
        float a0 = (vr - cc.x) * ie;
        float a1 = (vr - cc.y) * ie;
        { float m = m0, s = s0; LSE_STEP(a0); m0 = m; s0 = s; }
        { float m = m1, s = s1; LSE_STEP(a1); m1 = m; s1 = s; }
    }
    size_t base = (size_t)blockIdx.y * NN + 2 * col2;
    *(float2*)&g_partM[base] = make_float2(m0, m1);
    *(float2*)&g_partS[base] = make_float2(s0, s1);
}

// fp32 row-lse (extrapolation only).
__global__ void __launch_bounds__(256)
rowlse_kernel(const float* __restrict__ C, const float* __restrict__ v,
              const float* __restrict__ uold, float* __restrict__ uout,
              float cu, float cl) {
    __shared__ float vs[NN];
    __shared__ float redm[256], reds[256];
    int tid = threadIdx.x;
    for (int j = tid; j < NN; j += 256) vs[j] = v[j];
    __syncthreads();

    const float4* Crow = (const float4*)(C + (size_t)blockIdx.x * NN);
    float m = -CUDART_INF_F, s = 0.0f;
    const float ie = INVEPS();
#pragma unroll
    for (int jj = 0; jj < 8; jj++) {
        int j4 = tid + jj * 256;
        float4 cc = __ldcs(Crow + j4);
        float4 vv = *(const float4*)&vs[j4 << 2];
        float a;
        a = (vv.x - cc.x) * ie; LSE_STEP(a);
        a = (vv.y - cc.y) * ie; LSE_STEP(a);
        a = (vv.z - cc.z) * ie; LSE_STEP(a);
        a = (vv.w - cc.w) * ie; LSE_STEP(a);
    }
    redm[tid] = m; reds[tid] = s;
    __syncthreads();
    for (int o = 128; o > 0; o >>= 1) {
        if (tid < o) {
            float m2 = redm[tid + o], s2 = reds[tid + o];
            float M = fmaxf(m, m2);
            s = s * __expf(m - M) + s2 * __expf(m2 - M);
            m = M;
            redm[tid] = m; reds[tid] = s;
        }
        __syncthreads();
    }
    if (tid == 0)
        uout[blockIdx.x] = cu * uold[blockIdx.x] + cl * (__logf(s) + m + KLOG);
}

// fp32 column-lse pass 1 (extrapolation only).
__global__ void __launch_bounds__(256)
collse_part_kernel(const float* __restrict__ C, const float* __restrict__ v) {
    __shared__ float vsh[256];
    int tid = threadIdx.x;
    int col = blockIdx.x * 256 + tid;
    int r0 = blockIdx.y * 256;
    vsh[tid] = v[r0 + tid];
    __syncthreads();
    const float* Cp = C + (size_t)r0 * NN + col;
    float m = -CUDART_INF_F, s = 0.0f;
    const float ie = INVEPS();
#pragma unroll 8
    for (int r = 0; r < 256; r++) {
        float a = (vsh[r] - __ldcs(Cp)) * ie;
        Cp += NN;
        LSE_STEP(a);
    }
    g_partM[(size_t)blockIdx.y * NN + col] = m;
    g_partS[(size_t)blockIdx.y * NN + col] = s;
}

// Column-lse pass 2: combine 32 partials per column + apply update.
__global__ void __launch_bounds__(256)
collse_comb_kernel(const float* __restrict__ uold, float* __restrict__ uout,
                   float cu, float cl) {
    int j = blockIdx.x * 256 + threadIdx.x;
    float m = -CUDART_INF_F, s = 0.0f;
#pragma unroll
    for (int rc = 0; rc < 32; rc++) {
        float m2 = g_partM[(size_t)rc * NN + j];
        float s2 = g_partS[(size_t)rc * NN + j];
        float M = fmaxf(m, m2);
        s = s * __expf(m - M) + s2 * __expf(m2 - M);
        m = M;
    }
    uout[j] = cu * uold[j] + cl * (__logf(s) + m + KLOG);
}

__global__ void __launch_bounds__(256)
final_reduce_kernel(const float* __restrict__ fe, const float* __restrict__ pe,
                    const float* __restrict__ ge, const float* __restrict__ qe,
                    float* __restrict__ out) {
    __shared__ float sm[256];
    float s = 0.0f;
    for (int i = threadIdx.x; i < NN; i += 256)
        s += (fe[i] - pe[i]) + (ge[i] - qe[i]);
    sm[threadIdx.x] = s;
    __syncthreads();
    for (int o = 128; o > 0; o >>= 1) {
        if (threadIdx.x < o) sm[threadIdx.x] += sm[threadIdx.x + o];
        __syncthreads();
    }
    if (threadIdx.x == 0) out[0] = sm[0] * (1.0f / 8192.0f);
}

// ---------------- module preload at static-init -------------------------------
namespace {
struct ModulePreload {
    ModulePreload() {
        void* p = nullptr;
        cudaGetSymbolAddress(&p, g_Czx);
        (void)p;
    }
};
ModulePreload g_module_preload_;
}  // namespace

// ---------------- launch ------------------------------------------------------
extern "C" void kernel_launch(void* const* d_in, const int* in_sizes, int n_in,
                              void* d_out, int out_size) {
    const float* X = (const float*)d_in[0];   // x        (xt in reference)
    const float* Z = (const float*)d_in[1];   // prior_z  (xs in reference)
    float* out = (float*)d_out;

    float *Czx, *Czz, *Cxx, *Zr, *Xr, *nz, *nx, *vb;
    __half *Hzx, *Hzz, *Hxx;
    cudaGetSymbolAddress((void**)&Czx, g_Czx);
    cudaGetSymbolAddress((void**)&Czz, g_Czz);
    cudaGetSymbolAddress((void**)&Cxx, g_Cxx);
    cudaGetSymbolAddress((void**)&Hzx, g_Hzx);
    cudaGetSymbolAddress((void**)&Hzz, g_Hzz);
    cudaGetSymbolAddress((void**)&Hxx, g_Hxx);
    cudaGetSymbolAddress((void**)&Zr,  g_Zr);
    cudaGetSymbolAddress((void**)&Xr,  g_Xr);
    cudaGetSymbolAddress((void**)&nz,  g_nz);
    cudaGetSymbolAddress((void**)&nx,  g_nx);
    cudaGetSymbolAddress((void**)&vb,  g_vecbuf);

    cudaFuncSetAttribute(gemm_tc_kernel,
                         cudaFuncAttributeMaxDynamicSharedMemorySize, 65536);

    // --- setup: tf32 pre-round, fp32 norms, three distance matrices + diag fix ---
    preround_kernel<<<(NN * DD) / 256, 256>>>(Z, Zr);
    preround_kernel<<<(NN * DD) / 256, 256>>>(X, Xr);
    sqnorm_kernel<<<NN, 128>>>(Z, nz);
    sqnorm_kernel<<<NN, 128>>>(X, nx);
    dim3 gg(64, 64);
    gemm_tc_kernel<<<gg, 256, 65536>>>(Zr, Xr, nz, nx, Czx, Hzx);
    gemm_tc_kernel<<<gg, 256, 65536>>>(Zr, Zr, nz, nz, Czz, Hzz);
    gemm_tc_kernel<<<gg, 256, 65536>>>(Xr, Xr, nx, nx, Cxx, Hxx);
    diag_fix_kernel<<<NN / 8, 256>>>(Z, nz, Czz, Hzz);
    diag_fix_kernel<<<NN / 8, 256>>>(X, nx, Cxx, Hxx);

    // --- init potentials f,g,p,q = 0 in buffer 0 ---
    zero_kernel<<<(4 * NN) / 256, 256>>>(vb, 4 * NN);

    const float cu_it = 0.5f;
    const float cl_it = -0.5f * 0.05f;

    // --- 50 damped symmetric Sinkhorn iterations on fp16 costs ---
    for (int it = 0; it < 50; ++it) {
        float* A = vb + (it & 1) * 4 * NN;        // read (old carry)
        float* B = vb + ((it & 1) ^ 1) * 4 * NN;  // write (new carry)
        rowlse_h_kernel<<<NN, 256>>>(Hzx, A + NN, A, B, cu_it, cl_it);
        collse_part_h_kernel<<<dim3(16, 32), 256>>>(Hzx, A);
        collse_comb_kernel<<<32, 256>>>(A + NN, B + NN, cu_it, cl_it);
        rowlse_h_kernel<<<NN, 256>>>(Hzz, A + 2 * NN, A + 2 * NN, B + 2 * NN, cu_it, cl_it);
        rowlse_h_kernel<<<NN, 256>>>(Hxx, A + 3 * NN, A + 3 * NN, B + 3 * NN, cu_it, cl_it);
    }

    // --- extrapolation step on fp32 costs (final carry in buffer 0) ---
    {
        float* A = vb;             // final f,g,p,q
        float* E = vb + 4 * NN;    // f_e, g_e, p_e, q_e
        const float cu_e = 0.0f;
        const float cl_e = -0.05f;
        rowlse_kernel<<<NN, 256>>>(Czx, A + NN, A, E, cu_e, cl_e);                       // f_e
        collse_part_kernel<<<dim3(32, 32), 256>>>(Czx, A);
        collse_comb_kernel<<<32, 256>>>(A + NN, E + NN, cu_e, cl_e);                     // g_e
        rowlse_kernel<<<NN, 256>>>(Czz, A + 2 * NN, A + 2 * NN, E + 2 * NN, cu_e, cl_e); // p_e
        rowlse_kernel<<<NN, 256>>>(Cxx, A + 3 * NN, A + 3 * NN, E + 3 * NN, cu_e, cl_e); // q_e
        final_reduce_kernel<<<1, 256>>>(E, E + 2 * NN, E + NN, E + 3 * NN, out);
    }
}

// round 11
// speedup vs baseline: 1.8733x; 1.8733x over previous
#include <cuda_runtime.h>
#include <cuda_fp16.h>
#include <cstdint>
#include <math_constants.h>

#define NN 8192
#define DD 512

static __device__ __forceinline__ float INVEPS() { return 1.0f / 0.05f; }
#define KLOG  (-9.010913347279288f)    /* -ln(8192) */
#define K2F   (28.853900817779268f)    /* (1/eps) * log2(e) */
#define LN2F  (0.6931471805599453f)

__device__ __forceinline__ float ex2(float x) {
    float r;
    asm("ex2.approx.ftz.f32 %0, %1;" : "=f"(r) : "f"(x));
    return r;
}
__device__ __forceinline__ float lg2(float x) {
    float r;
    asm("lg2.approx.f32 %0, %1;" : "=f"(r) : "f"(x));
    return r;
}

// ---------------- static device scratch (no cudaMalloc allowed) -------------------
__device__ float  g_Czx[8192ull * 8192ull];   // fp32 (extrapolation)
__device__ float  g_Czz[8192ull * 8192ull];
__device__ float  g_Cxx[8192ull * 8192ull];
__device__ __half g_Hzx[8192ull * 8192ull];   // fp16 (iteration loop)
__device__ __half g_Hzz[8192ull * 8192ull];
__device__ __half g_Hxx[8192ull * 8192ull];
__device__ float  g_Zr[NN * DD];
__device__ float  g_Xr[NN * DD];
__device__ float  g_nz[NN];
__device__ float  g_nx[NN];
__device__ float  g_vecbuf[2 * 4 * NN];       // [buf][f,g,p,q][NN]
__device__ float  g_partM[32ull * NN];
__device__ float  g_partS[32ull * NN];

// ---------------- setup kernels ----------------------------------------------------

__global__ void __launch_bounds__(256) preround_kernel(const float* __restrict__ in,
                                                       float* __restrict__ out) {
    int i = blockIdx.x * 256 + threadIdx.x;
    if (i < NN * DD) {
        float v = in[i];
        uint32_t u;
        asm("cvt.rna.tf32.f32 %0, %1;" : "=r"(u) : "f"(v));
        out[i] = __uint_as_float(u);
    }
}

__global__ void __launch_bounds__(128) sqnorm_kernel(const float* __restrict__ X,
                                                     float* __restrict__ out) {
    __shared__ float sm[128];
    int r = blockIdx.x;
    const float4* row = (const float4*)(X + (size_t)r * DD);
    float4 v = row[threadIdx.x];
    float s = v.x * v.x + v.y * v.y + v.z * v.z + v.w * v.w;
    sm[threadIdx.x] = s;
    __syncthreads();
    for (int o = 64; o > 0; o >>= 1) {
        if (threadIdx.x < o) sm[threadIdx.x] += sm[threadIdx.x + o];
        __syncthreads();
    }
    if (threadIdx.x == 0) out[r] = sm[0];
}

// ---------------- TF32 tensor-core distance GEMM (dual fp32+fp16 output) ----------

#define SWZ(m, k) (((m) * 32) + ((k) ^ (((m) & 7) << 2)))

#define MMA_TF32(d, a, b0, b1)                                               \
    asm volatile(                                                            \
        "mma.sync.aligned.m16n8k8.row.col.f32.tf32.tf32.f32 "                \
        "{%0,%1,%2,%3},{%4,%5,%6,%7},{%8,%9},{%0,%1,%2,%3};"                 \
        : "+f"((d)[0]), "+f"((d)[1]), "+f"((d)[2]), "+f"((d)[3])             \
        : "r"((a)[0]), "r"((a)[1]), "r"((a)[2]), "r"((a)[3]),                \
          "r"(b0), "r"(b1))

__device__ __forceinline__ void cp_async16(uint32_t smem_addr, const float* gptr) {
    asm volatile("cp.async.cg.shared.global [%0], [%1], 16;\n"
                 :: "r"(smem_addr), "l"(gptr));
}

__device__ __forceinline__ void gemm_issue_stage(const float* __restrict__ A,
                                                 const float* __restrict__ B,
                                                 size_t rA, size_t rB, int k0,
                                                 float* dA, int tid) {
    float* dB = dA + 4096;
#pragma unroll
    for (int j = 0; j < 4; j++) {
        int idx = tid + 256 * j;
        int m = idx >> 3;
        int kq = idx & 7;
        uint32_t off = (uint32_t)(SWZ(m, kq * 4)) * 4u;
        uint32_t sa = (uint32_t)__cvta_generic_to_shared(dA) + off;
        uint32_t sb = (uint32_t)__cvta_generic_to_shared(dB) + off;
        cp_async16(sa, A + (rA + m) * DD + k0 + kq * 4);
        cp_async16(sb, B + (rB + m) * DD + k0 + kq * 4);
    }
    asm volatile("cp.async.commit_group;\n" ::);
}

__global__ void __launch_bounds__(256, 2)
gemm_tc_kernel(const float* __restrict__ A, const float* __restrict__ B,
               const float* __restrict__ na, const float* __restrict__ nb,
               float* __restrict__ C, __half* __restrict__ H) {
    extern __shared__ float smem[];
    int tid = threadIdx.x;
    int lane = tid & 31, w = tid >> 5;
    int wm = w >> 1, wn = w & 1;
    int g = lane >> 2, c = lane & 3;
    size_t rA = (size_t)blockIdx.y * 128;
    size_t rB = (size_t)blockIdx.x * 128;

    float acc[2][8][4] = {};

    gemm_issue_stage(A, B, rA, rB, 0, smem, tid);
    gemm_issue_stage(A, B, rA, rB, 32, smem + 8192, tid);

    for (int s = 0; s < 16; s++) {
        asm volatile("cp.async.wait_group 1;\n" ::);
        __syncthreads();
        {
            const float* As = smem + (s & 1) * 8192;
            const float* Bs = As + 4096;
#pragma unroll
            for (int k8 = 0; k8 < 4; k8++) {
                int kb = k8 * 8;
                uint32_t a[2][4];
#pragma unroll
                for (int mt = 0; mt < 2; mt++) {
                    int mb = wm * 32 + mt * 16;
                    a[mt][0] = __float_as_uint(As[SWZ(mb + g,     kb + c)]);
                    a[mt][1] = __float_as_uint(As[SWZ(mb + 8 + g, kb + c)]);
                    a[mt][2] = __float_as_uint(As[SWZ(mb + g,     kb + 4 + c)]);
                    a[mt][3] = __float_as_uint(As[SWZ(mb + 8 + g, kb + 4 + c)]);
                }
#pragma unroll
                for (int nt = 0; nt < 8; nt++) {
                    int nb_ = wn * 64 + nt * 8;
                    uint32_t b0 = __float_as_uint(Bs[SWZ(nb_ + g, kb + c)]);
                    uint32_t b1 = __float_as_uint(Bs[SWZ(nb_ + g, kb + 4 + c)]);
                    MMA_TF32(acc[0][nt], a[0], b0, b1);
                    MMA_TF32(acc[1][nt], a[1], b0, b1);
                }
            }
        }
        __syncthreads();
        if (s + 2 < 16)
            gemm_issue_stage(A, B, rA, rB, (s + 2) * 32, smem + ((s & 1) * 8192), tid);
        else
            asm volatile("cp.async.commit_group;\n" ::);
    }

#pragma unroll
    for (int mt = 0; mt < 2; mt++) {
        size_t m0 = rA + wm * 32 + mt * 16 + g;
        float na0 = __ldg(na + m0);
        float na1 = __ldg(na + m0 + 8);
#pragma unroll
        for (int nt = 0; nt < 8; nt++) {
            size_t n0 = rB + wn * 64 + nt * 8 + 2 * c;
            float nb0 = __ldg(nb + n0);
            float nb1 = __ldg(nb + n0 + 1);
            float2 o;
            o.x = sqrtf(fmaxf(na0 + nb0 - 2.0f * acc[mt][nt][0], 1e-12f));
            o.y = sqrtf(fmaxf(na0 + nb1 - 2.0f * acc[mt][nt][1], 1e-12f));
            __stcs((float2*)(C + m0 * NN + n0), o);
            *(__half2*)(H + m0 * NN + n0) = __float22half2_rn(o);
            o.x = sqrtf(fmaxf(na1 + nb0 - 2.0f * acc[mt][nt][2], 1e-12f));
            o.y = sqrtf(fmaxf(na1 + nb1 - 2.0f * acc[mt][nt][3], 1e-12f));
            __stcs((float2*)(C + (m0 + 8) * NN + n0), o);
            *(__half2*)(H + (m0 + 8) * NN + n0) = __float22half2_rn(o);
        }
    }
}

// fp32 diagonal fix (reduction order differs from sqnorm -> reference-like roundoff).
__global__ void __launch_bounds__(256)
diag_fix_kernel(const float* __restrict__ X, const float* __restrict__ n,
                float* __restrict__ C, __half* __restrict__ H) {
    int row = blockIdx.x * 8 + (threadIdx.x >> 5);
    int l = threadIdx.x & 31;
    const float* xr = X + (size_t)row * DD;
    float s = 0.0f;
#pragma unroll
    for (int k = 0; k < DD / 32; k++) {
        float v = xr[l + k * 32];
        s = fmaf(v, v, s);
    }
#pragma unroll
    for (int o = 16; o > 0; o >>= 1)
        s += __shfl_xor_sync(0xFFFFFFFFu, s, o);
    if (l == 0) {
        float d = sqrtf(fmaxf(2.0f * n[row] - 2.0f * s, 1e-12f));
        C[(size_t)row * NN + row] = d;
        H[(size_t)row * NN + row] = __float2half_rn(d);
    }
}

// ---------------- iteration-loop lse kernels (fp16, branch-free, base-2) ----------

__global__ void __launch_bounds__(256) zero_kernel(float* __restrict__ p, int n) {
    int i = blockIdx.x * 256 + threadIdx.x;
    if (i < n) p[i] = 0.0f;
}

// uout[i] = cu*uold[i] + cl*( eps_ln_lse + KLOG ), two-phase register LSE, base-2.
__global__ void __launch_bounds__(256)
rowlse_h2_kernel(const __half* __restrict__ C, const float* __restrict__ v,
                 const float* __restrict__ uold, float* __restrict__ uout,
                 float cu, float cl) {
    __shared__ float vs2[NN];          // v[j] * K2F
    __shared__ float redm[256], reds[256];
    int tid = threadIdx.x;
    for (int j = tid; j < NN; j += 256) vs2[j] = v[j] * K2F;
    __syncthreads();

    const uint4* Crow = (const uint4*)(C + (size_t)blockIdx.x * NN);
    float a[32];
#pragma unroll
    for (int jj = 0; jj < 4; jj++) {
        int u = tid + jj * 256;
        uint4 raw = __ldcs(Crow + u);
        const __half2* hp = (const __half2*)&raw;
        const float* vp = &vs2[u << 3];
#pragma unroll
        for (int q = 0; q < 4; q++) {
            float2 cf = __half22float2(hp[q]);
            a[jj * 8 + 2 * q]     = fmaf(cf.x, -K2F, vp[2 * q]);
            a[jj * 8 + 2 * q + 1] = fmaf(cf.y, -K2F, vp[2 * q + 1]);
        }
    }
    // tree max (non-destructive first level into mx[])
    float mx[16];
#pragma unroll
    for (int i = 0; i < 16; i++) mx[i] = fmaxf(a[i], a[i + 16]);
#pragma unroll
    for (int st = 8; st > 0; st >>= 1)
#pragma unroll
        for (int i = 0; i < 8; i++)
            if (i < st) mx[i] = fmaxf(mx[i], mx[i + st]);
    float m = mx[0];
    // sum of 2^(a-m), 4 accumulators
    float s0 = 0.0f, s1 = 0.0f, s2 = 0.0f, s3 = 0.0f;
#pragma unroll
    for (int i = 0; i < 32; i += 4) {
        s0 += ex2(a[i]     - m);
        s1 += ex2(a[i + 1] - m);
        s2 += ex2(a[i + 2] - m);
        s3 += ex2(a[i + 3] - m);
    }
    float s = (s0 + s1) + (s2 + s3);

    redm[tid] = m; reds[tid] = s;
    __syncthreads();
    for (int o = 128; o > 0; o >>= 1) {
        if (tid < o) {
            float m2 = redm[tid + o], s2b = reds[tid + o];
            float M = fmaxf(m, m2);
            s = s * ex2(m - M) + s2b * ex2(m2 - M);
            m = M;
            redm[tid] = m; reds[tid] = s;
        }
        __syncthreads();
    }
    if (tid == 0)
        uout[blockIdx.x] = cu * uold[blockIdx.x]
                         + cl * ((m + lg2(s)) * LN2F + KLOG);
}

// Column-lse pass 1 (fp16): branch-free online; thread = 2 cols via half2.
__global__ void __launch_bounds__(256)
collse_part_h2_kernel(const __half* __restrict__ C, const float* __restrict__ v) {
    __shared__ float fs2[256];
    int tid = threadIdx.x;
    int col2 = blockIdx.x * 256 + tid;
    int r0 = blockIdx.y * 256;
    fs2[tid] = v[r0 + tid] * K2F;
    __syncthreads();
    const __half2* Cp = (const __half2*)C + (size_t)r0 * (NN / 2) + col2;
    float m0 = -CUDART_INF_F, s0 = 0.0f, m1 = -CUDART_INF_F, s1 = 0.0f;
#pragma unroll 8
    for (int r = 0; r < 256; r++) {
        float2 cf = __half22float2(__ldcs(Cp));
        Cp += NN / 2;
        float pv = fs2[r];
        float a0 = fmaf(cf.x, -K2F, pv);
        float a1 = fmaf(cf.y, -K2F, pv);
        float M0 = fmaxf(m0, a0);
        s0 = s0 * ex2(m0 - M0) + ex2(a0 - M0);
        m0 = M0;
        float M1 = fmaxf(m1, a1);
        s1 = s1 * ex2(m1 - M1) + ex2(a1 - M1);
        m1 = M1;
    }
    size_t base = (size_t)blockIdx.y * NN + 2 * col2;
    *(float2*)&g_partM[base] = make_float2(m0, m1);
    *(float2*)&g_partS[base] = make_float2(s0, s1);
}

// Combine 32 partials per column (base-2) + apply update.
__global__ void __launch_bounds__(256)
collse_comb2_kernel(const float* __restrict__ uold, float* __restrict__ uout,
                    float cu, float cl) {
    int j = blockIdx.x * 256 + threadIdx.x;
    float m = -CUDART_INF_F, s = 0.0f;
#pragma unroll
    for (int rc = 0; rc < 32; rc++) {
        float m2 = g_partM[(size_t)rc * NN + j];
        float s2 = g_partS[(size_t)rc * NN + j];
        float M = fmaxf(m, m2);
        s = s * ex2(m - M) + s2 * ex2(m2 - M);
        m = M;
    }
    uout[j] = cu * uold[j] + cl * ((m + lg2(s)) * LN2F + KLOG);
}

// ---------------- extrapolation kernels (fp32, ln-domain, proven from R8) ----------

#define LSE_STEP(a) do { \
    if ((a) <= m) s += __expf((a) - m); \
    else { s = s * __expf(m - (a)) + 1.0f; m = (a); } } while (0)

__global__ void __launch_bounds__(256)
rowlse_kernel(const float* __restrict__ C, const float* __restrict__ v,
              const float* __restrict__ uold, float* __restrict__ uout,
              float cu, float cl) {
    __shared__ float vs[NN];
    __shared__ float redm[256], reds[256];
    int tid = threadIdx.x;
    for (int j = tid; j < NN; j += 256) vs[j] = v[j];
    __syncthreads();

    const float4* Crow = (const float4*)(C + (size_t)blockIdx.x * NN);
    float m = -CUDART_INF_F, s = 0.0f;
    const float ie = INVEPS();
#pragma unroll
    for (int jj = 0; jj < 8; jj++) {
        int j4 = tid + jj * 256;
        float4 cc = __ldcs(Crow + j4);
        float4 vv = *(const float4*)&vs[j4 << 2];
        float a;
        a = (vv.x - cc.x) * ie; LSE_STEP(a);
        a = (vv.y - cc.y) * ie; LSE_STEP(a);
        a = (vv.z - cc.z) * ie; LSE_STEP(a);
        a = (vv.w - cc.w) * ie; LSE_STEP(a);
    }
    redm[tid] = m; reds[tid] = s;
    __syncthreads();
    for (int o = 128; o > 0; o >>= 1) {
        if (tid < o) {
            float m2 = redm[tid + o], s2 = reds[tid + o];
            float M = fmaxf(m, m2);
            s = s * __expf(m - M) + s2 * __expf(m2 - M);
            m = M;
            redm[tid] = m; reds[tid] = s;
        }
        __syncthreads();
    }
    if (tid == 0)
        uout[blockIdx.x] = cu * uold[blockIdx.x] + cl * (__logf(s) + m + KLOG);
}

__global__ void __launch_bounds__(256)
collse_part_kernel(const float* __restrict__ C, const float* __restrict__ v) {
    __shared__ float vsh[256];
    int tid = threadIdx.x;
    int col = blockIdx.x * 256 + tid;
    int r0 = blockIdx.y * 256;
    vsh[tid] = v[r0 + tid];
    __syncthreads();
    const float* Cp = C + (size_t)r0 * NN + col;
    float m = -CUDART_INF_F, s = 0.0f;
    const float ie = INVEPS();
#pragma unroll 8
    for (int r = 0; r < 256; r++) {
        float a = (vsh[r] - __ldcs(Cp)) * ie;
        Cp += NN;
        LSE_STEP(a);
    }
    g_partM[(size_t)blockIdx.y * NN + col] = m;
    g_partS[(size_t)blockIdx.y * NN + col] = s;
}

__global__ void __launch_bounds__(256)
collse_comb_kernel(const float* __restrict__ uold, float* __restrict__ uout,
                   float cu, float cl) {
    int j = blockIdx.x * 256 + threadIdx.x;
    float m = -CUDART_INF_F, s = 0.0f;
#pragma unroll
    for (int rc = 0; rc < 32; rc++) {
        float m2 = g_partM[(size_t)rc * NN + j];
        float s2 = g_partS[(size_t)rc * NN + j];
        float M = fmaxf(m, m2);
        s = s * __expf(m - M) + s2 * __expf(m2 - M);
        m = M;
    }
    uout[j] = cu * uold[j] + cl * (__logf(s) + m + KLOG);
}

__global__ void __launch_bounds__(256)
final_reduce_kernel(const float* __restrict__ fe, const float* __restrict__ pe,
                    const float* __restrict__ ge, const float* __restrict__ qe,
                    float* __restrict__ out) {
    __shared__ float sm[256];
    float s = 0.0f;
    for (int i = threadIdx.x; i < NN; i += 256)
        s += (fe[i] - pe[i]) + (ge[i] - qe[i]);
    sm[threadIdx.x] = s;
    __syncthreads();
    for (int o = 128; o > 0; o >>= 1) {
        if (threadIdx.x < o) sm[threadIdx.x] += sm[threadIdx.x + o];
        __syncthreads();
    }
    if (threadIdx.x == 0) out[0] = sm[0] * (1.0f / 8192.0f);
}

// ---------------- module preload at static-init -------------------------------
namespace {
struct ModulePreload {
    ModulePreload() {
        void* p = nullptr;
        cudaGetSymbolAddress(&p, g_Czx);
        (void)p;
    }
};
ModulePreload g_module_preload_;
}  // namespace

// ---------------- launch ------------------------------------------------------
extern "C" void kernel_launch(void* const* d_in, const int* in_sizes, int n_in,
                              void* d_out, int out_size) {
    const float* X = (const float*)d_in[0];   // x        (xt)
    const float* Z = (const float*)d_in[1];   // prior_z  (xs)
    float* out = (float*)d_out;

    float *Czx, *Czz, *Cxx, *Zr, *Xr, *nz, *nx, *vb;
    __half *Hzx, *Hzz, *Hxx;
    cudaGetSymbolAddress((void**)&Czx, g_Czx);
    cudaGetSymbolAddress((void**)&Czz, g_Czz);
    cudaGetSymbolAddress((void**)&Cxx, g_Cxx);
    cudaGetSymbolAddress((void**)&Hzx, g_Hzx);
    cudaGetSymbolAddress((void**)&Hzz, g_Hzz);
    cudaGetSymbolAddress((void**)&Hxx, g_Hxx);
    cudaGetSymbolAddress((void**)&Zr,  g_Zr);
    cudaGetSymbolAddress((void**)&Xr,  g_Xr);
    cudaGetSymbolAddress((void**)&nz,  g_nz);
    cudaGetSymbolAddress((void**)&nx,  g_nx);
    cudaGetSymbolAddress((void**)&vb,  g_vecbuf);

    cudaFuncSetAttribute(gemm_tc_kernel,
                         cudaFuncAttributeMaxDynamicSharedMemorySize, 65536);

    // --- setup ---
    preround_kernel<<<(NN * DD) / 256, 256>>>(Z, Zr);
    preround_kernel<<<(NN * DD) / 256, 256>>>(X, Xr);
    sqnorm_kernel<<<NN, 128>>>(Z, nz);
    sqnorm_kernel<<<NN, 128>>>(X, nx);
    dim3 gg(64, 64);
    gemm_tc_kernel<<<gg, 256, 65536>>>(Zr, Xr, nz, nx, Czx, Hzx);
    gemm_tc_kernel<<<gg, 256, 65536>>>(Zr, Zr, nz, nz, Czz, Hzz);
    gemm_tc_kernel<<<gg, 256, 65536>>>(Xr, Xr, nx, nx, Cxx, Hxx);
    diag_fix_kernel<<<NN / 8, 256>>>(Z, nz, Czz, Hzz);
    diag_fix_kernel<<<NN / 8, 256>>>(X, nx, Cxx, Hxx);

    zero_kernel<<<(4 * NN) / 256, 256>>>(vb, 4 * NN);

    const float cu_it = 0.5f;
    const float cl_it = -0.5f * 0.05f;

    // --- 50 damped symmetric Sinkhorn iterations (fp16 costs, branch-free lse) ---
    for (int it = 0; it < 50; ++it) {
        float* A = vb + (it & 1) * 4 * NN;
        float* B = vb + ((it & 1) ^ 1) * 4 * NN;
        rowlse_h2_kernel<<<NN, 256>>>(Hzx, A + NN, A, B, cu_it, cl_it);
        collse_part_h2_kernel<<<dim3(16, 32), 256>>>(Hzx, A);
        collse_comb2_kernel<<<32, 256>>>(A + NN, B + NN, cu_it, cl_it);
        rowlse_h2_kernel<<<NN, 256>>>(Hzz, A + 2 * NN, A + 2 * NN, B + 2 * NN, cu_it, cl_it);
        rowlse_h2_kernel<<<NN, 256>>>(Hxx, A + 3 * NN, A + 3 * NN, B + 3 * NN, cu_it, cl_it);
    }

    // --- extrapolation on fp32 costs (final carry in buffer 0) ---
    {
        float* A = vb;
        float* E = vb + 4 * NN;
        const float cu_e = 0.0f;
        const float cl_e = -0.05f;
        rowlse_kernel<<<NN, 256>>>(Czx, A + NN, A, E, cu_e, cl_e);                       // f_e
        collse_part_kernel<<<dim3(32, 32), 256>>>(Czx, A);
        collse_comb_kernel<<<32, 256>>>(A + NN, E + NN, cu_e, cl_e);                     // g_e
        rowlse_kernel<<<NN, 256>>>(Czz, A + 2 * NN, A + 2 * NN, E + 2 * NN, cu_e, cl_e); // p_e
        rowlse_kernel<<<NN, 256>>>(Cxx, A + 3 * NN, A + 3 * NN, E + 3 * NN, cu_e, cl_e); // q_e
        final_reduce_kernel<<<1, 256>>>(E, E + 2 * NN, E + NN, E + 3 * NN, out);
    }
}

// round 13
// speedup vs baseline: 1.9377x; 1.0344x over previous
#include <cuda_runtime.h>
#include <cuda_fp16.h>
#include <cstdint>
#include <math_constants.h>

#define NN 8192
#define DD 512

static __device__ __forceinline__ float INVEPS() { return 1.0f / 0.05f; }
#define KLOG  (-9.010913347279288f)    /* -ln(8192) */
#define K2F   (28.853900817779268f)    /* (1/eps) * log2(e) */
#define LN2F  (0.6931471805599453f)

__device__ __forceinline__ float ex2(float x) {
    float r;
    asm("ex2.approx.ftz.f32 %0, %1;" : "=f"(r) : "f"(x));
    return r;
}
__device__ __forceinline__ float lg2(float x) {
    float r;
    asm("lg2.approx.f32 %0, %1;" : "=f"(r) : "f"(x));
    return r;
}

// ---------------- static device scratch (no cudaMalloc allowed) -------------------
__device__ float  g_Czx[8192ull * 8192ull];   // fp32 (extrapolation)
__device__ float  g_Czz[8192ull * 8192ull];
__device__ float  g_Cxx[8192ull * 8192ull];
__device__ __half g_Hzx[8192ull * 8192ull];   // fp16 (iteration loop)
__device__ __half g_Hzz[8192ull * 8192ull];
__device__ __half g_Hxx[8192ull * 8192ull];
__device__ float  g_Zr[NN * DD];
__device__ float  g_Xr[NN * DD];
__device__ float  g_nz[NN];
__device__ float  g_nx[NN];
__device__ float  g_vecbuf[2 * 4 * NN];       // [buf][f,g,p,q][NN]
__device__ float  g_partM[32ull * NN];
__device__ float  g_partS[32ull * NN];

// ---------------- setup kernels ----------------------------------------------------

__global__ void __launch_bounds__(256) preround_kernel(const float* __restrict__ in,
                                                       float* __restrict__ out) {
    int i = blockIdx.x * 256 + threadIdx.x;
    if (i < NN * DD) {
        float v = in[i];
        uint32_t u;
        asm("cvt.rna.tf32.f32 %0, %1;" : "=r"(u) : "f"(v));
        out[i] = __uint_as_float(u);
    }
}

__global__ void __launch_bounds__(128) sqnorm_kernel(const float* __restrict__ X,
                                                     float* __restrict__ out) {
    __shared__ float sm[128];
    int r = blockIdx.x;
    const float4* row = (const float4*)(X + (size_t)r * DD);
    float4 v = row[threadIdx.x];
    float s = v.x * v.x + v.y * v.y + v.z * v.z + v.w * v.w;
    sm[threadIdx.x] = s;
    __syncthreads();
    for (int o = 64; o > 0; o >>= 1) {
        if (threadIdx.x < o) sm[threadIdx.x] += sm[threadIdx.x + o];
        __syncthreads();
    }
    if (threadIdx.x == 0) out[r] = sm[0];
}

// ---------------- TF32 tensor-core distance GEMM (dual fp32+fp16 output) ----------
// symm != 0: only bx >= by tiles computed; off-diag tiles mirrored via smem transpose.

#define SWZ(m, k) (((m) * 32) + ((k) ^ (((m) & 7) << 2)))

#define MMA_TF32(d, a, b0, b1)                                               \
    asm volatile(                                                            \
        "mma.sync.aligned.m16n8k8.row.col.f32.tf32.tf32.f32 "                \
        "{%0,%1,%2,%3},{%4,%5,%6,%7},{%8,%9},{%0,%1,%2,%3};"                 \
        : "+f"((d)[0]), "+f"((d)[1]), "+f"((d)[2]), "+f"((d)[3])             \
        : "r"((a)[0]), "r"((a)[1]), "r"((a)[2]), "r"((a)[3]),                \
          "r"(b0), "r"(b1))

__device__ __forceinline__ void cp_async16(uint32_t smem_addr, const float* gptr) {
    asm volatile("cp.async.cg.shared.global [%0], [%1], 16;\n"
                 :: "r"(smem_addr), "l"(gptr));
}

__device__ __forceinline__ void gemm_issue_stage(const float* __restrict__ A,
                                                 const float* __restrict__ B,
                                                 size_t rA, size_t rB, int k0,
                                                 float* dA, int tid) {
    float* dB = dA + 4096;
#pragma unroll
    for (int j = 0; j < 4; j++) {
        int idx = tid + 256 * j;
        int m = idx >> 3;
        int kq = idx & 7;
        uint32_t off = (uint32_t)(SWZ(m, kq * 4)) * 4u;
        uint32_t sa = (uint32_t)__cvta_generic_to_shared(dA) + off;
        uint32_t sb = (uint32_t)__cvta_generic_to_shared(dB) + off;
        cp_async16(sa, A + (rA + m) * DD + k0 + kq * 4);
        cp_async16(sb, B + (rB + m) * DD + k0 + kq * 4);
    }
    asm volatile("cp.async.commit_group;\n" ::);
}

__global__ void __launch_bounds__(256, 2)
gemm_tc_kernel(const float* __restrict__ A, const float* __restrict__ B,
               const float* __restrict__ na, const float* __restrict__ nb,
               float* __restrict__ C, __half* __restrict__ H, int symm) {
    int bx = blockIdx.x, by = blockIdx.y;
    if (symm && bx < by) return;

    extern __shared__ float smem[];
    int tid = threadIdx.x;
    int lane = tid & 31, w = tid >> 5;
    int wm = w >> 1, wn = w & 1;
    int g = lane >> 2, c = lane & 3;
    size_t rA = (size_t)by * 128;
    size_t rB = (size_t)bx * 128;

    float acc[2][8][4] = {};

    gemm_issue_stage(A, B, rA, rB, 0, smem, tid);
    gemm_issue_stage(A, B, rA, rB, 32, smem + 8192, tid);

    for (int s = 0; s < 16; s++) {
        asm volatile("cp.async.wait_group 1;\n" ::);
        __syncthreads();
        {
            const float* As = smem + (s & 1) * 8192;
            const float* Bs = As + 4096;
#pragma unroll
            for (int k8 = 0; k8 < 4; k8++) {
                int kb = k8 * 8;
                uint32_t a[2][4];
#pragma unroll
                for (int mt = 0; mt < 2; mt++) {
                    int mb = wm * 32 + mt * 16;
                    a[mt][0] = __float_as_uint(As[SWZ(mb + g,     kb + c)]);
                    a[mt][1] = __float_as_uint(As[SWZ(mb + 8 + g, kb + c)]);
                    a[mt][2] = __float_as_uint(As[SWZ(mb + g,     kb + 4 + c)]);
                    a[mt][3] = __float_as_uint(As[SWZ(mb + 8 + g, kb + 4 + c)]);
                }
#pragma unroll
                for (int nt = 0; nt < 8; nt++) {
                    int nb_ = wn * 64 + nt * 8;
                    uint32_t b0 = __float_as_uint(Bs[SWZ(nb_ + g, kb + c)]);
                    uint32_t b1 = __float_as_uint(Bs[SWZ(nb_ + g, kb + 4 + c)]);
                    MMA_TF32(acc[0][nt], a[0], b0, b1);
                    MMA_TF32(acc[1][nt], a[1], b0, b1);
                }
            }
        }
        __syncthreads();
        if (s + 2 < 16)
            gemm_issue_stage(A, B, rA, rB, (s + 2) * 32, smem + ((s & 1) * 8192), tid);
        else
            asm volatile("cp.async.commit_group;\n" ::);
    }

    asm volatile("cp.async.wait_group 0;\n" ::);
    __syncthreads();   // smem free for transpose staging

    if (!symm) {
        // plain epilogue: direct fp32 + fp16 writes
#pragma unroll
        for (int mt = 0; mt < 2; mt++) {
            size_t m0 = rA + wm * 32 + mt * 16 + g;
            float na0 = __ldg(na + m0);
            float na1 = __ldg(na + m0 + 8);
#pragma unroll
            for (int nt = 0; nt < 8; nt++) {
                size_t n0 = rB + wn * 64 + nt * 8 + 2 * c;
                float nb0 = __ldg(nb + n0);
                float nb1 = __ldg(nb + n0 + 1);
                float2 o;
                o.x = sqrtf(fmaxf(na0 + nb0 - 2.0f * acc[mt][nt][0], 1e-12f));
                o.y = sqrtf(fmaxf(na0 + nb1 - 2.0f * acc[mt][nt][1], 1e-12f));
                __stcs((float2*)(C + m0 * NN + n0), o);
                *(__half2*)(H + m0 * NN + n0) = __float22half2_rn(o);
                o.x = sqrtf(fmaxf(na1 + nb0 - 2.0f * acc[mt][nt][2], 1e-12f));
                o.y = sqrtf(fmaxf(na1 + nb1 - 2.0f * acc[mt][nt][3], 1e-12f));
                __stcs((float2*)(C + (m0 + 8) * NN + n0), o);
                *(__half2*)(H + (m0 + 8) * NN + n0) = __float22half2_rn(o);
            }
        }
        return;
    }

    // symmetric epilogue: direct writes + smem-transposed mirror (64 n-rows/half)
    for (int half = 0; half < 2; half++) {
        if (wn == half) {
#pragma unroll
            for (int mt = 0; mt < 2; mt++) {
                int ml0 = wm * 32 + mt * 16 + g;     // 0..127 local m
                size_t m0 = rA + ml0;
                float na0 = __ldg(na + m0);
                float na1 = __ldg(na + m0 + 8);
#pragma unroll
                for (int nt = 0; nt < 8; nt++) {
                    int nl = nt * 8 + 2 * c;         // 0..63 within half
                    size_t n0 = rB + half * 64 + nl;
                    float nb0 = __ldg(nb + n0);
                    float nb1 = __ldg(nb + n0 + 1);
                    float2 o;
                    o.x = sqrtf(fmaxf(na0 + nb0 - 2.0f * acc[mt][nt][0], 1e-12f));
                    o.y = sqrtf(fmaxf(na0 + nb1 - 2.0f * acc[mt][nt][1], 1e-12f));
                    __stcs((float2*)(C + m0 * NN + n0), o);
                    *(__half2*)(H + m0 * NN + n0) = __float22half2_rn(o);
                    smem[nl * 132 + ml0]       = o.x;
                    smem[(nl + 1) * 132 + ml0] = o.y;
                    o.x = sqrtf(fmaxf(na1 + nb0 - 2.0f * acc[mt][nt][2], 1e-12f));
                    o.y = sqrtf(fmaxf(na1 + nb1 - 2.0f * acc[mt][nt][3], 1e-12f));
                    __stcs((float2*)(C + (m0 + 8) * NN + n0), o);
                    *(__half2*)(H + (m0 + 8) * NN + n0) = __float22half2_rn(o);
                    smem[nl * 132 + ml0 + 8]       = o.x;
                    smem[(nl + 1) * 132 + ml0 + 8] = o.y;
                }
            }
        }
        __syncthreads();
        if (bx != by) {
            // mirror: rows rB+half*64 .. +63, cols rA .. rA+127
            for (int idx = tid; idx < 64 * 32; idx += 256) {
                int row = idx >> 5, c4 = (idx & 31) << 2;
                float4 v = *(const float4*)&smem[row * 132 + c4];
                size_t gr = rB + half * 64 + row;
                __stcs((float4*)(C + gr * NN + rA + c4), v);
                __half2 h0 = __float22half2_rn(make_float2(v.x, v.y));
                __half2 h1 = __float22half2_rn(make_float2(v.z, v.w));
                uint2 pk;
                pk.x = *(uint32_t*)&h0;
                pk.y = *(uint32_t*)&h1;
                *(uint2*)(H + gr * NN + rA + c4) = pk;
            }
        }
        __syncthreads();
    }
}

// fp32 diagonal fix (reduction order differs from sqnorm -> reference-like roundoff).
__global__ void __launch_bounds__(256)
diag_fix_kernel(const float* __restrict__ X, const float* __restrict__ n,
                float* __restrict__ C, __half* __restrict__ H) {
    int row = blockIdx.x * 8 + (threadIdx.x >> 5);
    int l = threadIdx.x & 31;
    const float* xr = X + (size_t)row * DD;
    float s = 0.0f;
#pragma unroll
    for (int k = 0; k < DD / 32; k++) {
        float v = xr[l + k * 32];
        s = fmaf(v, v, s);
    }
#pragma unroll
    for (int o = 16; o > 0; o >>= 1)
        s += __shfl_xor_sync(0xFFFFFFFFu, s, o);
    if (l == 0) {
        float d = sqrtf(fmaxf(2.0f * n[row] - 2.0f * s, 1e-12f));
        C[(size_t)row * NN + row] = d;
        H[(size_t)row * NN + row] = __float2half_rn(d);
    }
}

// ---------------- iteration-loop lse kernels (fp16, branch-free, base-2) ----------

__global__ void __launch_bounds__(256) zero_kernel(float* __restrict__ p, int n) {
    int i = blockIdx.x * 256 + threadIdx.x;
    if (i < n) p[i] = 0.0f;
}

__global__ void __launch_bounds__(256)
rowlse_h2_kernel(const __half* __restrict__ C, const float* __restrict__ v,
                 const float* __restrict__ uold, float* __restrict__ uout,
                 float cu, float cl) {
    __shared__ float vs2[NN];          // v[j] * K2F
    __shared__ float redm[256], reds[256];
    int tid = threadIdx.x;
    for (int j = tid; j < NN; j += 256) vs2[j] = v[j] * K2F;
    __syncthreads();

    const uint4* Crow = (const uint4*)(C + (size_t)blockIdx.x * NN);
    float a[32];
#pragma unroll
    for (int jj = 0; jj < 4; jj++) {
        int u = tid + jj * 256;
        uint4 raw = __ldcs(Crow + u);
        const __half2* hp = (const __half2*)&raw;
        const float* vp = &vs2[u << 3];
#pragma unroll
        for (int q = 0; q < 4; q++) {
            float2 cf = __half22float2(hp[q]);
            a[jj * 8 + 2 * q]     = fmaf(cf.x, -K2F, vp[2 * q]);
            a[jj * 8 + 2 * q + 1] = fmaf(cf.y, -K2F, vp[2 * q + 1]);
        }
    }
    float mx[16];
#pragma unroll
    for (int i = 0; i < 16; i++) mx[i] = fmaxf(a[i], a[i + 16]);
#pragma unroll
    for (int st = 8; st > 0; st >>= 1)
#pragma unroll
        for (int i = 0; i < 8; i++)
            if (i < st) mx[i] = fmaxf(mx[i], mx[i + st]);
    float m = mx[0];
    float s0 = 0.0f, s1 = 0.0f, s2 = 0.0f, s3 = 0.0f;
#pragma unroll
    for (int i = 0; i < 32; i += 4) {
        s0 += ex2(a[i]     - m);
        s1 += ex2(a[i + 1] - m);
        s2 += ex2(a[i + 2] - m);
        s3 += ex2(a[i + 3] - m);
    }
    float s = (s0 + s1) + (s2 + s3);

    redm[tid] = m; reds[tid] = s;
    __syncthreads();
    for (int o = 128; o > 0; o >>= 1) {
        if (tid < o) {
            float m2 = redm[tid + o], s2b = reds[tid + o];
            float M = fmaxf(m, m2);
            s = s * ex2(m - M) + s2b * ex2(m2 - M);
            m = M;
            redm[tid] = m; reds[tid] = s;
        }
        __syncthreads();
    }
    if (tid == 0)
        uout[blockIdx.x] = cu * uold[blockIdx.x]
                         + cl * ((m + lg2(s)) * LN2F + KLOG);
}

__global__ void __launch_bounds__(256)
collse_part_h2_kernel(const __half* __restrict__ C, const float* __restrict__ v) {
    __shared__ float fs2[256];
    int tid = threadIdx.x;
    int col2 = blockIdx.x * 256 + tid;
    int r0 = blockIdx.y * 256;
    fs2[tid] = v[r0 + tid] * K2F;
    __syncthreads();
    const __half2* Cp = (const __half2*)C + (size_t)r0 * (NN / 2) + col2;
    float m0 = -CUDART_INF_F, s0 = 0.0f, m1 = -CUDART_INF_F, s1 = 0.0f;
#pragma unroll 8
    for (int r = 0; r < 256; r++) {
        float2 cf = __half22float2(__ldcs(Cp));
        Cp += NN / 2;
        float pv = fs2[r];
        float a0 = fmaf(cf.x, -K2F, pv);
        float a1 = fmaf(cf.y, -K2F, pv);
        float M0 = fmaxf(m0, a0);
        s0 = s0 * ex2(m0 - M0) + ex2(a0 - M0);
        m0 = M0;
        float M1 = fmaxf(m1, a1);
        s1 = s1 * ex2(m1 - M1) + ex2(a1 - M1);
        m1 = M1;
    }
    size_t base = (size_t)blockIdx.y * NN + 2 * col2;
    *(float2*)&g_partM[base] = make_float2(m0, m1);
    *(float2*)&g_partS[base] = make_float2(s0, s1);
}

// Combine 32 partials per column (base-2) + apply update.
__global__ void __launch_bounds__(256)
collse_comb2_kernel(const float* __restrict__ uold, float* __restrict__ uout,
                    float cu, float cl) {
    int j = blockIdx.x * 256 + threadIdx.x;
    float m = -CUDART_INF_F, s = 0.0f;
#pragma unroll
    for (int rc = 0; rc < 32; rc++) {
        float m2 = g_partM[(size_t)rc * NN + j];
        float s2 = g_partS[(size_t)rc * NN + j];
        float M = fmaxf(m, m2);
        s = s * ex2(m - M) + s2 * ex2(m2 - M);
        m = M;
    }
    uout[j] = cu * uold[j] + cl * ((m + lg2(s)) * LN2F + KLOG);
}

// ---------------- extrapolation kernels (fp32, branch-free, base-2) ---------------

__global__ void __launch_bounds__(256)
rowlse_f2_kernel(const float* __restrict__ C, const float* __restrict__ v,
                 const float* __restrict__ uold, float* __restrict__ uout,
                 float cu, float cl) {
    __shared__ float vs2[NN];
    __shared__ float redm[256], reds[256];
    int tid = threadIdx.x;
    for (int j = tid; j < NN; j += 256) vs2[j] = v[j] * K2F;
    __syncthreads();

    const float4* Crow = (const float4*)(C + (size_t)blockIdx.x * NN);
    float a[32];
#pragma unroll
    for (int jj = 0; jj < 8; jj++) {
        int u = tid + jj * 256;
        float4 cc = __ldcs(Crow + u);
        const float* vp = &vs2[u << 2];
        a[jj * 4 + 0] = fmaf(cc.x, -K2F, vp[0]);
        a[jj * 4 + 1] = fmaf(cc.y, -K2F, vp[1]);
        a[jj * 4 + 2] = fmaf(cc.z, -K2F, vp[2]);
        a[jj * 4 + 3] = fmaf(cc.w, -K2F, vp[3]);
    }
    float mx[16];
#pragma unroll
    for (int i = 0; i < 16; i++) mx[i] = fmaxf(a[i], a[i + 16]);
#pragma unroll
    for (int st = 8; st > 0; st >>= 1)
#pragma unroll
        for (int i = 0; i < 8; i++)
            if (i < st) mx[i] = fmaxf(mx[i], mx[i + st]);
    float m = mx[0];
    float s0 = 0.0f, s1 = 0.0f, s2 = 0.0f, s3 = 0.0f;
#pragma unroll
    for (int i = 0; i < 32; i += 4) {
        s0 += ex2(a[i]     - m);
        s1 += ex2(a[i + 1] - m);
        s2 += ex2(a[i + 2] - m);
        s3 += ex2(a[i + 3] - m);
    }
    float s = (s0 + s1) + (s2 + s3);

    redm[tid] = m; reds[tid] = s;
    __syncthreads();
    for (int o = 128; o > 0; o >>= 1) {
        if (tid < o) {
            float m2 = redm[tid + o], s2b = reds[tid + o];
            float M = fmaxf(m, m2);
            s = s * ex2(m - M) + s2b * ex2(m2 - M);
            m = M;
            redm[tid] = m; reds[tid] = s;
        }
        __syncthreads();
    }
    if (tid == 0)
        uout[blockIdx.x] = cu * uold[blockIdx.x]
                         + cl * ((m + lg2(s)) * LN2F + KLOG);
}

__global__ void __launch_bounds__(256)
collse_part_f2_kernel(const float* __restrict__ C, const float* __restrict__ v) {
    __shared__ float fs2[256];
    int tid = threadIdx.x;
    int col = blockIdx.x * 256 + tid;
    int r0 = blockIdx.y * 256;
    fs2[tid] = v[r0 + tid] * K2F;
    __syncthreads();
    const float* Cp = C + (size_t)r0 * NN + col;
    float m = -CUDART_INF_F, s = 0.0f;
#pragma unroll 8
    for (int r = 0; r < 256; r++) {
        float a = fmaf(__ldcs(Cp), -K2F, fs2[r]);
        Cp += NN;
        float M = fmaxf(m, a);
        s = s * ex2(m - M) + ex2(a - M);
        m = M;
    }
    g_partM[(size_t)blockIdx.y * NN + col] = m;
    g_partS[(size_t)blockIdx.y * NN + col] = s;
}

__global__ void __launch_bounds__(256)
final_reduce_kernel(const float* __restrict__ fe, const float* __restrict__ pe,
                    const float* __restrict__ ge, const float* __restrict__ qe,
                    float* __restrict__ out) {
    __shared__ float sm[256];
    float s = 0.0f;
    for (int i = threadIdx.x; i < NN; i += 256)
        s += (fe[i] - pe[i]) + (ge[i] - qe[i]);
    sm[threadIdx.x] = s;
    __syncthreads();
    for (int o = 128; o > 0; o >>= 1) {
        if (threadIdx.x < o) sm[threadIdx.x] += sm[threadIdx.x + o];
        __syncthreads();
    }
    if (threadIdx.x == 0) out[0] = sm[0] * (1.0f / 8192.0f);
}

// ---------------- module preload at static-init -------------------------------
namespace {
struct ModulePreload {
    ModulePreload() {
        void* p = nullptr;
        cudaGetSymbolAddress(&p, g_Czx);
        (void)p;
    }
};
ModulePreload g_module_preload_;
}  // namespace

// ---------------- launch ------------------------------------------------------
extern "C" void kernel_launch(void* const* d_in, const int* in_sizes, int n_in,
                              void* d_out, int out_size) {
    const float* X = (const float*)d_in[0];   // x        (xt)
    const float* Z = (const float*)d_in[1];   // prior_z  (xs)
    float* out = (float*)d_out;

    float *Czx, *Czz, *Cxx, *Zr, *Xr, *nz, *nx, *vb;
    __half *Hzx, *Hzz, *Hxx;
    cudaGetSymbolAddress((void**)&Czx, g_Czx);
    cudaGetSymbolAddress((void**)&Czz, g_Czz);
    cudaGetSymbolAddress((void**)&Cxx, g_Cxx);
    cudaGetSymbolAddress((void**)&Hzx, g_Hzx);
    cudaGetSymbolAddress((void**)&Hzz, g_Hzz);
    cudaGetSymbolAddress((void**)&Hxx, g_Hxx);
    cudaGetSymbolAddress((void**)&Zr,  g_Zr);
    cudaGetSymbolAddress((void**)&Xr,  g_Xr);
    cudaGetSymbolAddress((void**)&nz,  g_nz);
    cudaGetSymbolAddress((void**)&nx,  g_nx);
    cudaGetSymbolAddress((void**)&vb,  g_vecbuf);

    cudaFuncSetAttribute(gemm_tc_kernel,
                         cudaFuncAttributeMaxDynamicSharedMemorySize, 65536);

    // --- setup ---
    preround_kernel<<<(NN * DD) / 256, 256>>>(Z, Zr);
    preround_kernel<<<(NN * DD) / 256, 256>>>(X, Xr);
    sqnorm_kernel<<<NN, 128>>>(Z, nz);
    sqnorm_kernel<<<NN, 128>>>(X, nx);
    dim3 gg(64, 64);
    gemm_tc_kernel<<<gg, 256, 65536>>>(Zr, Xr, nz, nx, Czx, Hzx, 0);
    gemm_tc_kernel<<<gg, 256, 65536>>>(Zr, Zr, nz, nz, Czz, Hzz, 1);
    gemm_tc_kernel<<<gg, 256, 65536>>>(Xr, Xr, nx, nx, Cxx, Hxx, 1);
    diag_fix_kernel<<<NN / 8, 256>>>(Z, nz, Czz, Hzz);
    diag_fix_kernel<<<NN / 8, 256>>>(X, nx, Cxx, Hxx);

    zero_kernel<<<(4 * NN) / 256, 256>>>(vb, 4 * NN);

    const float cu_it = 0.5f;
    const float cl_it = -0.5f * 0.05f;

    // --- 50 damped symmetric Sinkhorn iterations (fp16 costs, branch-free lse) ---
    for (int it = 0; it < 50; ++it) {
        float* A = vb + (it & 1) * 4 * NN;
        float* B = vb + ((it & 1) ^ 1) * 4 * NN;
        rowlse_h2_kernel<<<NN, 256>>>(Hzx, A + NN, A, B, cu_it, cl_it);
        collse_part_h2_kernel<<<dim3(16, 32), 256>>>(Hzx, A);
        collse_comb2_kernel<<<32, 256>>>(A + NN, B + NN, cu_it, cl_it);
        rowlse_h2_kernel<<<NN, 256>>>(Hzz, A + 2 * NN, A + 2 * NN, B + 2 * NN, cu_it, cl_it);
        rowlse_h2_kernel<<<NN, 256>>>(Hxx, A + 3 * NN, A + 3 * NN, B + 3 * NN, cu_it, cl_it);
    }

    // --- extrapolation on fp32 costs (final carry in buffer 0) ---
    {
        float* A = vb;
        float* E = vb + 4 * NN;
        const float cu_e = 0.0f;
        const float cl_e = -0.05f;
        rowlse_f2_kernel<<<NN, 256>>>(Czx, A + NN, A, E, cu_e, cl_e);                       // f_e
        collse_part_f2_kernel<<<dim3(32, 32), 256>>>(Czx, A);
        collse_comb2_kernel<<<32, 256>>>(A + NN, E + NN, cu_e, cl_e);                       // g_e
        rowlse_f2_kernel<<<NN, 256>>>(Czz, A + 2 * NN, A + 2 * NN, E + 2 * NN, cu_e, cl_e); // p_e
        rowlse_f2_kernel<<<NN, 256>>>(Cxx, A + 3 * NN, A + 3 * NN, E + 3 * NN, cu_e, cl_e); // q_e
        final_reduce_kernel<<<1, 256>>>(E, E + 2 * NN, E + NN, E + 3 * NN, out);
    }
}

// round 14
// speedup vs baseline: 2.9216x; 1.5078x over previous
#include <cuda_runtime.h>
#include <cuda_fp16.h>
#include <cstdint>
#include <math_constants.h>

#define NN 8192
#define DD 512

#define KLOG  (-9.010913347279288f)    /* -ln(8192) */
#define K2F   (28.853900817779268f)    /* (1/eps) * log2(e) */
#define LN2F  (0.6931471805599453f)

__device__ __forceinline__ float ex2(float x) {
    float r;
    asm("ex2.approx.ftz.f32 %0, %1;" : "=f"(r) : "f"(x));
    return r;
}
__device__ __forceinline__ float lg2(float x) {
    float r;
    asm("lg2.approx.f32 %0, %1;" : "=f"(r) : "f"(x));
    return r;
}

// ---------------- static device scratch (no cudaMalloc allowed) -------------------
__device__ float  g_Czx[8192ull * 8192ull];   // fp32 (extrapolation)
__device__ float  g_Czz[8192ull * 8192ull];
__device__ float  g_Cxx[8192ull * 8192ull];
__device__ __half g_Hzx[8192ull * 8192ull];   // fp16 (iteration loop)
__device__ __half g_Hzz[8192ull * 8192ull];
__device__ __half g_Hxx[8192ull * 8192ull];
__device__ float  g_Zr[NN * DD];
__device__ float  g_Xr[NN * DD];
__device__ float  g_nz[NN];
__device__ float  g_nx[NN];
__device__ float  g_vecbuf[2 * 4 * NN];       // [buf][f,g,p,q][NN]
__device__ float  g_partM[32ull * NN];
__device__ float  g_partS[32ull * NN];

// ---------------- setup kernels ----------------------------------------------------

__global__ void __launch_bounds__(256) preround_kernel(const float* __restrict__ in,
                                                       float* __restrict__ out) {
    int i = blockIdx.x * 256 + threadIdx.x;
    if (i < NN * DD) {
        float v = in[i];
        uint32_t u;
        asm("cvt.rna.tf32.f32 %0, %1;" : "=r"(u) : "f"(v));
        out[i] = __uint_as_float(u);
    }
}

__global__ void __launch_bounds__(128) sqnorm_kernel(const float* __restrict__ X,
                                                     float* __restrict__ out) {
    __shared__ float sm[128];
    int r = blockIdx.x;
    const float4* row = (const float4*)(X + (size_t)r * DD);
    float4 v = row[threadIdx.x];
    float s = v.x * v.x + v.y * v.y + v.z * v.z + v.w * v.w;
    sm[threadIdx.x] = s;
    __syncthreads();
    for (int o = 64; o > 0; o >>= 1) {
        if (threadIdx.x < o) sm[threadIdx.x] += sm[threadIdx.x + o];
        __syncthreads();
    }
    if (threadIdx.x == 0) out[r] = sm[0];
}

// ---------------- TF32 tensor-core distance GEMM (dual fp32+fp16 output) ----------
// symm != 0: only bx >= by tiles computed; off-diag tiles mirrored via smem transpose.

#define SWZ(m, k) (((m) * 32) + ((k) ^ (((m) & 7) << 2)))

#define MMA_TF32(d, a, b0, b1)                                               \
    asm volatile(                                                            \
        "mma.sync.aligned.m16n8k8.row.col.f32.tf32.tf32.f32 "                \
        "{%0,%1,%2,%3},{%4,%5,%6,%7},{%8,%9},{%0,%1,%2,%3};"                 \
        : "+f"((d)[0]), "+f"((d)[1]), "+f"((d)[2]), "+f"((d)[3])             \
        : "r"((a)[0]), "r"((a)[1]), "r"((a)[2]), "r"((a)[3]),                \
          "r"(b0), "r"(b1))

__device__ __forceinline__ void cp_async16(uint32_t smem_addr, const float* gptr) {
    asm volatile("cp.async.cg.shared.global [%0], [%1], 16;\n"
                 :: "r"(smem_addr), "l"(gptr));
}

__device__ __forceinline__ void gemm_issue_stage(const float* __restrict__ A,
                                                 const float* __restrict__ B,
                                                 size_t rA, size_t rB, int k0,
                                                 float* dA, int tid) {
    float* dB = dA + 4096;
#pragma unroll
    for (int j = 0; j < 4; j++) {
        int idx = tid + 256 * j;
        int m = idx >> 3;
        int kq = idx & 7;
        uint32_t off = (uint32_t)(SWZ(m, kq * 4)) * 4u;
        uint32_t sa = (uint32_t)__cvta_generic_to_shared(dA) + off;
        uint32_t sb = (uint32_t)__cvta_generic_to_shared(dB) + off;
        cp_async16(sa, A + (rA + m) * DD + k0 + kq * 4);
        cp_async16(sb, B + (rB + m) * DD + k0 + kq * 4);
    }
    asm volatile("cp.async.commit_group;\n" ::);
}

__global__ void __launch_bounds__(256, 2)
gemm_tc_kernel(const float* __restrict__ A, const float* __restrict__ B,
               const float* __restrict__ na, const float* __restrict__ nb,
               float* __restrict__ C, __half* __restrict__ H, int symm) {
    int bx = blockIdx.x, by = blockIdx.y;
    if (symm && bx < by) return;

    extern __shared__ float smem[];
    int tid = threadIdx.x;
    int lane = tid & 31, w = tid >> 5;
    int wm = w >> 1, wn = w & 1;
    int g = lane >> 2, c = lane & 3;
    size_t rA = (size_t)by * 128;
    size_t rB = (size_t)bx * 128;

    float acc[2][8][4] = {};

    gemm_issue_stage(A, B, rA, rB, 0, smem, tid);
    gemm_issue_stage(A, B, rA, rB, 32, smem + 8192, tid);

    for (int s = 0; s < 16; s++) {
        asm volatile("cp.async.wait_group 1;\n" ::);
        __syncthreads();
        {
            const float* As = smem + (s & 1) * 8192;
            const float* Bs = As + 4096;
#pragma unroll
            for (int k8 = 0; k8 < 4; k8++) {
                int kb = k8 * 8;
                uint32_t a[2][4];
#pragma unroll
                for (int mt = 0; mt < 2; mt++) {
                    int mb = wm * 32 + mt * 16;
                    a[mt][0] = __float_as_uint(As[SWZ(mb + g,     kb + c)]);
                    a[mt][1] = __float_as_uint(As[SWZ(mb + 8 + g, kb + c)]);
                    a[mt][2] = __float_as_uint(As[SWZ(mb + g,     kb + 4 + c)]);
                    a[mt][3] = __float_as_uint(As[SWZ(mb + 8 + g, kb + 4 + c)]);
                }
#pragma unroll
                for (int nt = 0; nt < 8; nt++) {
                    int nb_ = wn * 64 + nt * 8;
                    uint32_t b0 = __float_as_uint(Bs[SWZ(nb_ + g, kb + c)]);
                    uint32_t b1 = __float_as_uint(Bs[SWZ(nb_ + g, kb + 4 + c)]);
                    MMA_TF32(acc[0][nt], a[0], b0, b1);
                    MMA_TF32(acc[1][nt], a[1], b0, b1);
                }
            }
        }
        __syncthreads();
        if (s + 2 < 16)
            gemm_issue_stage(A, B, rA, rB, (s + 2) * 32, smem + ((s & 1) * 8192), tid);
        else
            asm volatile("cp.async.commit_group;\n" ::);
    }

    asm volatile("cp.async.wait_group 0;\n" ::);
    __syncthreads();   // smem free for transpose staging

    if (!symm) {
#pragma unroll
        for (int mt = 0; mt < 2; mt++) {
            size_t m0 = rA + wm * 32 + mt * 16 + g;
            float na0 = __ldg(na + m0);
            float na1 = __ldg(na + m0 + 8);
#pragma unroll
            for (int nt = 0; nt < 8; nt++) {
                size_t n0 = rB + wn * 64 + nt * 8 + 2 * c;
                float nb0 = __ldg(nb + n0);
                float nb1 = __ldg(nb + n0 + 1);
                float2 o;
                o.x = sqrtf(fmaxf(na0 + nb0 - 2.0f * acc[mt][nt][0], 1e-12f));
                o.y = sqrtf(fmaxf(na0 + nb1 - 2.0f * acc[mt][nt][1], 1e-12f));
                __stcs((float2*)(C + m0 * NN + n0), o);
                *(__half2*)(H + m0 * NN + n0) = __float22half2_rn(o);
                o.x = sqrtf(fmaxf(na1 + nb0 - 2.0f * acc[mt][nt][2], 1e-12f));
                o.y = sqrtf(fmaxf(na1 + nb1 - 2.0f * acc[mt][nt][3], 1e-12f));
                __stcs((float2*)(C + (m0 + 8) * NN + n0), o);
                *(__half2*)(H + (m0 + 8) * NN + n0) = __float22half2_rn(o);
            }
        }
        return;
    }

    // symmetric epilogue: direct writes + smem-transposed mirror (64 n-rows/half)
    for (int half = 0; half < 2; half++) {
        if (wn == half) {
#pragma unroll
            for (int mt = 0; mt < 2; mt++) {
                int ml0 = wm * 32 + mt * 16 + g;     // 0..127 local m
                size_t m0 = rA + ml0;
                float na0 = __ldg(na + m0);
                float na1 = __ldg(na + m0 + 8);
#pragma unroll
                for (int nt = 0; nt < 8; nt++) {
                    int nl = nt * 8 + 2 * c;         // 0..63 within half
                    size_t n0 = rB + half * 64 + nl;
                    float nb0 = __ldg(nb + n0);
                    float nb1 = __ldg(nb + n0 + 1);
                    float2 o;
                    o.x = sqrtf(fmaxf(na0 + nb0 - 2.0f * acc[mt][nt][0], 1e-12f));
                    o.y = sqrtf(fmaxf(na0 + nb1 - 2.0f * acc[mt][nt][1], 1e-12f));
                    __stcs((float2*)(C + m0 * NN + n0), o);
                    *(__half2*)(H + m0 * NN + n0) = __float22half2_rn(o);
                    smem[nl * 132 + ml0]       = o.x;
                    smem[(nl + 1) * 132 + ml0] = o.y;
                    o.x = sqrtf(fmaxf(na1 + nb0 - 2.0f * acc[mt][nt][2], 1e-12f));
                    o.y = sqrtf(fmaxf(na1 + nb1 - 2.0f * acc[mt][nt][3], 1e-12f));
                    __stcs((float2*)(C + (m0 + 8) * NN + n0), o);
                    *(__half2*)(H + (m0 + 8) * NN + n0) = __float22half2_rn(o);
                    smem[nl * 132 + ml0 + 8]       = o.x;
                    smem[(nl + 1) * 132 + ml0 + 8] = o.y;
                }
            }
        }
        __syncthreads();
        if (bx != by) {
            for (int idx = tid; idx < 64 * 32; idx += 256) {
                int row = idx >> 5, c4 = (idx & 31) << 2;
                float4 v = *(const float4*)&smem[row * 132 + c4];
                size_t gr = rB + half * 64 + row;
                __stcs((float4*)(C + gr * NN + rA + c4), v);
                __half2 h0 = __float22half2_rn(make_float2(v.x, v.y));
                __half2 h1 = __float22half2_rn(make_float2(v.z, v.w));
                uint2 pk;
                pk.x = *(uint32_t*)&h0;
                pk.y = *(uint32_t*)&h1;
                *(uint2*)(H + gr * NN + rA + c4) = pk;
            }
        }
        __syncthreads();
    }
}

// fp32 diagonal fix (reduction order differs from sqnorm -> reference-like roundoff).
__global__ void __launch_bounds__(256)
diag_fix_kernel(const float* __restrict__ X, const float* __restrict__ n,
                float* __restrict__ C, __half* __restrict__ H) {
    int row = blockIdx.x * 8 + (threadIdx.x >> 5);
    int l = threadIdx.x & 31;
    const float* xr = X + (size_t)row * DD;
    float s = 0.0f;
#pragma unroll
    for (int k = 0; k < DD / 32; k++) {
        float v = xr[l + k * 32];
        s = fmaf(v, v, s);
    }
#pragma unroll
    for (int o = 16; o > 0; o >>= 1)
        s += __shfl_xor_sync(0xFFFFFFFFu, s, o);
    if (l == 0) {
        float d = sqrtf(fmaxf(2.0f * n[row] - 2.0f * s, 1e-12f));
        C[(size_t)row * NN + row] = d;
        H[(size_t)row * NN + row] = __float2half_rn(d);
    }
}

// ---------------- iteration-loop lse kernels (fp16, branch-free, base-2) ----------

__global__ void __launch_bounds__(256) zero_kernel(float* __restrict__ p, int n) {
    int i = blockIdx.x * 256 + threadIdx.x;
    if (i < n) p[i] = 0.0f;
}

// Fused 3-matrix row-lse: grid (NN, 3). y=0: f from (Hzx, g); y=1: p from (Hzz, p);
// y=2: q from (Hxx, q). No smem v-preload (v served from L1), warp-shfl tail.
__global__ void __launch_bounds__(256)
rowlse3_kernel(const __half* __restrict__ Hzx, const __half* __restrict__ Hzz,
               const __half* __restrict__ Hxx, const float* __restrict__ A,
               float* __restrict__ B, float cu, float cl) {
    int y = blockIdx.y;
    const __half* C = (y == 0) ? Hzx : (y == 1) ? Hzz : Hxx;
    const float* v  = A + ((y == 0) ? NN : (y == 1) ? 2 * NN : 3 * NN);
    const float* uo = (y == 0) ? A : v;
    float* uout     = B + ((y == 0) ? 0 : (y == 1) ? 2 * NN : 3 * NN);

    __shared__ float redm[8], reds[8];
    int tid = threadIdx.x;
    int lane = tid & 31, wid = tid >> 5;
    int row = blockIdx.x;

    const uint4* Crow = (const uint4*)(C + (size_t)row * NN);
    const float4* v4 = (const float4*)v;
    float a[32];
#pragma unroll
    for (int jj = 0; jj < 4; jj++) {
        int u = tid + jj * 256;
        uint4 raw = __ldcs(Crow + u);
        float4 v01 = __ldg(v4 + 2 * u);
        float4 v23 = __ldg(v4 + 2 * u + 1);
        const __half2* hp = (const __half2*)&raw;
        float2 c0 = __half22float2(hp[0]);
        float2 c1 = __half22float2(hp[1]);
        float2 c2 = __half22float2(hp[2]);
        float2 c3 = __half22float2(hp[3]);
        a[jj * 8 + 0] = (v01.x - c0.x) * K2F;
        a[jj * 8 + 1] = (v01.y - c0.y) * K2F;
        a[jj * 8 + 2] = (v01.z - c1.x) * K2F;
        a[jj * 8 + 3] = (v01.w - c1.y) * K2F;
        a[jj * 8 + 4] = (v23.x - c2.x) * K2F;
        a[jj * 8 + 5] = (v23.y - c2.y) * K2F;
        a[jj * 8 + 6] = (v23.z - c3.x) * K2F;
        a[jj * 8 + 7] = (v23.w - c3.y) * K2F;
    }
    float mx[16];
#pragma unroll
    for (int i = 0; i < 16; i++) mx[i] = fmaxf(a[i], a[i + 16]);
#pragma unroll
    for (int st = 8; st > 0; st >>= 1)
#pragma unroll
        for (int i = 0; i < 8; i++)
            if (i < st) mx[i] = fmaxf(mx[i], mx[i + st]);
    float m = mx[0];
    float s0 = 0.0f, s1 = 0.0f, s2 = 0.0f, s3 = 0.0f;
#pragma unroll
    for (int i = 0; i < 32; i += 4) {
        s0 += ex2(a[i]     - m);
        s1 += ex2(a[i + 1] - m);
        s2 += ex2(a[i + 2] - m);
        s3 += ex2(a[i + 3] - m);
    }
    float s = (s0 + s1) + (s2 + s3);

    // warp shfl reduce
#pragma unroll
    for (int o = 16; o > 0; o >>= 1) {
        float m2 = __shfl_xor_sync(0xFFFFFFFFu, m, o);
        float sb = __shfl_xor_sync(0xFFFFFFFFu, s, o);
        float M = fmaxf(m, m2);
        s = s * ex2(m - M) + sb * ex2(m2 - M);
        m = M;
    }
    if (lane == 0) { redm[wid] = m; reds[wid] = s; }
    __syncthreads();
    if (tid == 0) {
        m = redm[0]; s = reds[0];
#pragma unroll
        for (int i = 1; i < 8; i++) {
            float m2 = redm[i], sb = reds[i];
            float M = fmaxf(m, m2);
            s = s * ex2(m - M) + sb * ex2(m2 - M);
            m = M;
        }
        uout[row] = cu * uo[row] + cl * ((m + lg2(s)) * LN2F + KLOG);
    }
}

__global__ void __launch_bounds__(256)
collse_part_h2_kernel(const __half* __restrict__ C, const float* __restrict__ v) {
    __shared__ float fs2[256];
    int tid = threadIdx.x;
    int col2 = blockIdx.x * 256 + tid;
    int r0 = blockIdx.y * 256;
    fs2[tid] = v[r0 + tid] * K2F;
    __syncthreads();
    const __half2* Cp = (const __half2*)C + (size_t)r0 * (NN / 2) + col2;
    float m0 = -CUDART_INF_F, s0 = 0.0f, m1 = -CUDART_INF_F, s1 = 0.0f;
#pragma unroll 8
    for (int r = 0; r < 256; r++) {
        float2 cf = __half22float2(__ldcs(Cp));
        Cp += NN / 2;
        float pv = fs2[r];
        float a0 = fmaf(cf.x, -K2F, pv);
        float a1 = fmaf(cf.y, -K2F, pv);
        float M0 = fmaxf(m0, a0);
        s0 = s0 * ex2(m0 - M0) + ex2(a0 - M0);
        m0 = M0;
        float M1 = fmaxf(m1, a1);
        s1 = s1 * ex2(m1 - M1) + ex2(a1 - M1);
        m1 = M1;
    }
    size_t base = (size_t)blockIdx.y * NN + 2 * col2;
    *(float2*)&g_partM[base] = make_float2(m0, m1);
    *(float2*)&g_partS[base] = make_float2(s0, s1);
}

// Combine 32 partials per column (base-2) + apply update.
__global__ void __launch_bounds__(256)
collse_comb2_kernel(const float* __restrict__ uold, float* __restrict__ uout,
                    float cu, float cl) {
    int j = blockIdx.x * 256 + threadIdx.x;
    float m = -CUDART_INF_F, s = 0.0f;
#pragma unroll
    for (int rc = 0; rc < 32; rc++) {
        float m2 = g_partM[(size_t)rc * NN + j];
        float s2 = g_partS[(size_t)rc * NN + j];
        float M = fmaxf(m, m2);
        s = s * ex2(m - M) + s2 * ex2(m2 - M);
        m = M;
    }
    uout[j] = cu * uold[j] + cl * ((m + lg2(s)) * LN2F + KLOG);
}

// ---------------- extrapolation kernels (fp32, branch-free, base-2) ---------------

__global__ void __launch_bounds__(256)
rowlse_f2_kernel(const float* __restrict__ C, const float* __restrict__ v,
                 const float* __restrict__ uold, float* __restrict__ uout,
                 float cu, float cl) {
    __shared__ float vs2[NN];
    __shared__ float redm[256], reds[256];
    int tid = threadIdx.x;
    for (int j = tid; j < NN; j += 256) vs2[j] = v[j] * K2F;
    __syncthreads();

    const float4* Crow = (const float4*)(C + (size_t)blockIdx.x * NN);
    float a[32];
#pragma unroll
    for (int jj = 0; jj < 8; jj++) {
        int u = tid + jj * 256;
        float4 cc = __ldcs(Crow + u);
        const float* vp = &vs2[u << 2];
        a[jj * 4 + 0] = fmaf(cc.x, -K2F, vp[0]);
        a[jj * 4 + 1] = fmaf(cc.y, -K2F, vp[1]);
        a[jj * 4 + 2] = fmaf(cc.z, -K2F, vp[2]);
        a[jj * 4 + 3] = fmaf(cc.w, -K2F, vp[3]);
    }
    float mx[16];
#pragma unroll
    for (int i = 0; i < 16; i++) mx[i] = fmaxf(a[i], a[i + 16]);
#pragma unroll
    for (int st = 8; st > 0; st >>= 1)
#pragma unroll
        for (int i = 0; i < 8; i++)
            if (i < st) mx[i] = fmaxf(mx[i], mx[i + st]);
    float m = mx[0];
    float s0 = 0.0f, s1 = 0.0f, s2 = 0.0f, s3 = 0.0f;
#pragma unroll
    for (int i = 0; i < 32; i += 4) {
        s0 += ex2(a[i]     - m);
        s1 += ex2(a[i + 1] - m);
        s2 += ex2(a[i + 2] - m);
        s3 += ex2(a[i + 3] - m);
    }
    float s = (s0 + s1) + (s2 + s3);

    redm[tid] = m; reds[tid] = s;
    __syncthreads();
    for (int o = 128; o > 0; o >>= 1) {
        if (tid < o) {
            float m2 = redm[tid + o], s2b = reds[tid + o];
            float M = fmaxf(m, m2);
            s = s * ex2(m - M) + s2b * ex2(m2 - M);
            m = M;
            redm[tid] = m; reds[tid] = s;
        }
        __syncthreads();
    }
    if (tid == 0)
        uout[blockIdx.x] = cu * uold[blockIdx.x]
                         + cl * ((m + lg2(s)) * LN2F + KLOG);
}

__global__ void __launch_bounds__(256)
collse_part_f2_kernel(const float* __restrict__ C, const float* __restrict__ v) {
    __shared__ float fs2[256];
    int tid = threadIdx.x;
    int col = blockIdx.x * 256 + tid;
    int r0 = blockIdx.y * 256;
    fs2[tid] = v[r0 + tid] * K2F;
    __syncthreads();
    const float* Cp = C + (size_t)r0 * NN + col;
    float m = -CUDART_INF_F, s = 0.0f;
#pragma unroll 8
    for (int r = 0; r < 256; r++) {
        float a = fmaf(__ldcs(Cp), -K2F, fs2[r]);
        Cp += NN;
        float M = fmaxf(m, a);
        s = s * ex2(m - M) + ex2(a - M);
        m = M;
    }
    g_partM[(size_t)blockIdx.y * NN + col] = m;
    g_partS[(size_t)blockIdx.y * NN + col] = s;
}

__global__ void __launch_bounds__(256)
final_reduce_kernel(const float* __restrict__ fe, const float* __restrict__ pe,
                    const float* __restrict__ ge, const float* __restrict__ qe,
                    float* __restrict__ out) {
    __shared__ float sm[256];
    float s = 0.0f;
    for (int i = threadIdx.x; i < NN; i += 256)
        s += (fe[i] - pe[i]) + (ge[i] - qe[i]);
    sm[threadIdx.x] = s;
    __syncthreads();
    for (int o = 128; o > 0; o >>= 1) {
        if (threadIdx.x < o) sm[threadIdx.x] += sm[threadIdx.x + o];
        __syncthreads();
    }
    if (threadIdx.x == 0) out[0] = sm[0] * (1.0f / 8192.0f);
}

// ---------------- module preload at static-init -------------------------------
namespace {
struct ModulePreload {
    ModulePreload() {
        void* p = nullptr;
        cudaGetSymbolAddress(&p, g_Czx);
        (void)p;
    }
};
ModulePreload g_module_preload_;
}  // namespace

// ---------------- launch ------------------------------------------------------
extern "C" void kernel_launch(void* const* d_in, const int* in_sizes, int n_in,
                              void* d_out, int out_size) {
    const float* X = (const float*)d_in[0];   // x        (xt)
    const float* Z = (const float*)d_in[1];   // prior_z  (xs)
    float* out = (float*)d_out;

    float *Czx, *Czz, *Cxx, *Zr, *Xr, *nz, *nx, *vb;
    __half *Hzx, *Hzz, *Hxx;
    cudaGetSymbolAddress((void**)&Czx, g_Czx);
    cudaGetSymbolAddress((void**)&Czz, g_Czz);
    cudaGetSymbolAddress((void**)&Cxx, g_Cxx);
    cudaGetSymbolAddress((void**)&Hzx, g_Hzx);
    cudaGetSymbolAddress((void**)&Hzz, g_Hzz);
    cudaGetSymbolAddress((void**)&Hxx, g_Hxx);
    cudaGetSymbolAddress((void**)&Zr,  g_Zr);
    cudaGetSymbolAddress((void**)&Xr,  g_Xr);
    cudaGetSymbolAddress((void**)&nz,  g_nz);
    cudaGetSymbolAddress((void**)&nx,  g_nx);
    cudaGetSymbolAddress((void**)&vb,  g_vecbuf);

    cudaFuncSetAttribute(gemm_tc_kernel,
                         cudaFuncAttributeMaxDynamicSharedMemorySize, 65536);

    // --- setup ---
    preround_kernel<<<(NN * DD) / 256, 256>>>(Z, Zr);
    preround_kernel<<<(NN * DD) / 256, 256>>>(X, Xr);
    sqnorm_kernel<<<NN, 128>>>(Z, nz);
    sqnorm_kernel<<<NN, 128>>>(X, nx);
    dim3 gg(64, 64);
    gemm_tc_kernel<<<gg, 256, 65536>>>(Zr, Xr, nz, nx, Czx, Hzx, 0);
    gemm_tc_kernel<<<gg, 256, 65536>>>(Zr, Zr, nz, nz, Czz, Hzz, 1);
    gemm_tc_kernel<<<gg, 256, 65536>>>(Xr, Xr, nx, nx, Cxx, Hxx, 1);
    diag_fix_kernel<<<NN / 8, 256>>>(Z, nz, Czz, Hzz);
    diag_fix_kernel<<<NN / 8, 256>>>(X, nx, Cxx, Hxx);

    zero_kernel<<<(4 * NN) / 256, 256>>>(vb, 4 * NN);

    const float cu_it = 0.5f;
    const float cl_it = -0.5f * 0.05f;

    // --- 50 damped symmetric Sinkhorn iterations (3 kernels/iter) ---
    for (int it = 0; it < 50; ++it) {
        float* A = vb + (it & 1) * 4 * NN;
        float* B = vb + ((it & 1) ^ 1) * 4 * NN;
        rowlse3_kernel<<<dim3(NN, 3), 256>>>(Hzx, Hzz, Hxx, A, B, cu_it, cl_it);
        collse_part_h2_kernel<<<dim3(16, 32), 256>>>(Hzx, A);
        collse_comb2_kernel<<<32, 256>>>(A + NN, B + NN, cu_it, cl_it);
    }

    // --- extrapolation on fp32 costs (final carry in buffer 0) ---
    {
        float* A = vb;
        float* E = vb + 4 * NN;
        const float cu_e = 0.0f;
        const float cl_e = -0.05f;
        rowlse_f2_kernel<<<NN, 256>>>(Czx, A + NN, A, E, cu_e, cl_e);                       // f_e
        collse_part_f2_kernel<<<dim3(32, 32), 256>>>(Czx, A);
        collse_comb2_kernel<<<32, 256>>>(A + NN, E + NN, cu_e, cl_e);                       // g_e
        rowlse_f2_kernel<<<NN, 256>>>(Czz, A + 2 * NN, A + 2 * NN, E + 2 * NN, cu_e, cl_e); // p_e
        rowlse_f2_kernel<<<NN, 256>>>(Cxx, A + 3 * NN, A + 3 * NN, E + 3 * NN, cu_e, cl_e); // q_e
        final_reduce_kernel<<<1, 256>>>(E, E + 2 * NN, E + NN, E + 3 * NN, out);
    }
}

// round 15
// speedup vs baseline: 3.1969x; 1.0942x over previous
#include <cuda_runtime.h>
#include <cuda_fp16.h>
#include <cstdint>
#include <math_constants.h>

#define NN 8192
#define DD 512

#define KLOG  (-9.010913347279288f)    /* -ln(8192) */
#define K2F   (28.853900817779268f)    /* (1/eps) * log2(e) */
#define LN2F  (0.6931471805599453f)

__device__ __forceinline__ float ex2(float x) {
    float r;
    asm("ex2.approx.ftz.f32 %0, %1;" : "=f"(r) : "f"(x));
    return r;
}
__device__ __forceinline__ float lg2(float x) {
    float r;
    asm("lg2.approx.f32 %0, %1;" : "=f"(r) : "f"(x));
    return r;
}

// ---------------- static device scratch (no cudaMalloc allowed) -------------------
__device__ __half g_Hzx[8192ull * 8192ull];   // fp16 cost matrices (loop + extrapolation)
__device__ __half g_Hzz[8192ull * 8192ull];
__device__ __half g_Hxx[8192ull * 8192ull];
__device__ float  g_Zr[NN * DD];              // tf32-rounded inputs
__device__ float  g_Xr[NN * DD];
__device__ float  g_nz[NN];                   // fp32 row sq-norms (original inputs)
__device__ float  g_nx[NN];
__device__ float  g_vecbuf[2 * 4 * NN];       // [buf][f,g,p,q][NN]
__device__ float  g_partM[32ull * NN];
__device__ float  g_partS[32ull * NN];

// ---------------- setup kernels ----------------------------------------------------

__global__ void __launch_bounds__(256) preround_kernel(const float* __restrict__ in,
                                                       float* __restrict__ out) {
    int i = blockIdx.x * 256 + threadIdx.x;
    if (i < NN * DD) {
        float v = in[i];
        uint32_t u;
        asm("cvt.rna.tf32.f32 %0, %1;" : "=r"(u) : "f"(v));
        out[i] = __uint_as_float(u);
    }
}

__global__ void __launch_bounds__(128) sqnorm_kernel(const float* __restrict__ X,
                                                     float* __restrict__ out) {
    __shared__ float sm[128];
    int r = blockIdx.x;
    const float4* row = (const float4*)(X + (size_t)r * DD);
    float4 v = row[threadIdx.x];
    float s = v.x * v.x + v.y * v.y + v.z * v.z + v.w * v.w;
    sm[threadIdx.x] = s;
    __syncthreads();
    for (int o = 64; o > 0; o >>= 1) {
        if (threadIdx.x < o) sm[threadIdx.x] += sm[threadIdx.x + o];
        __syncthreads();
    }
    if (threadIdx.x == 0) out[r] = sm[0];
}

// ---------------- TF32 tensor-core distance GEMM (fp16 output) --------------------
// symm != 0: only bx >= by tiles computed; off-diag tiles mirrored via smem transpose.

#define SWZ(m, k) (((m) * 32) + ((k) ^ (((m) & 7) << 2)))

#define MMA_TF32(d, a, b0, b1)                                               \
    asm volatile(                                                            \
        "mma.sync.aligned.m16n8k8.row.col.f32.tf32.tf32.f32 "                \
        "{%0,%1,%2,%3},{%4,%5,%6,%7},{%8,%9},{%0,%1,%2,%3};"                 \
        : "+f"((d)[0]), "+f"((d)[1]), "+f"((d)[2]), "+f"((d)[3])             \
        : "r"((a)[0]), "r"((a)[1]), "r"((a)[2]), "r"((a)[3]),                \
          "r"(b0), "r"(b1))

__device__ __forceinline__ void cp_async16(uint32_t smem_addr, const float* gptr) {
    asm volatile("cp.async.cg.shared.global [%0], [%1], 16;\n"
                 :: "r"(smem_addr), "l"(gptr));
}

__device__ __forceinline__ void gemm_issue_stage(const float* __restrict__ A,
                                                 const float* __restrict__ B,
                                                 size_t rA, size_t rB, int k0,
                                                 float* dA, int tid) {
    float* dB = dA + 4096;
#pragma unroll
    for (int j = 0; j < 4; j++) {
        int idx = tid + 256 * j;
        int m = idx >> 3;
        int kq = idx & 7;
        uint32_t off = (uint32_t)(SWZ(m, kq * 4)) * 4u;
        uint32_t sa = (uint32_t)__cvta_generic_to_shared(dA) + off;
        uint32_t sb = (uint32_t)__cvta_generic_to_shared(dB) + off;
        cp_async16(sa, A + (rA + m) * DD + k0 + kq * 4);
        cp_async16(sb, B + (rB + m) * DD + k0 + kq * 4);
    }
    asm volatile("cp.async.commit_group;\n" ::);
}

__global__ void __launch_bounds__(256, 2)
gemm_tc_kernel(const float* __restrict__ A, const float* __restrict__ B,
               const float* __restrict__ na, const float* __restrict__ nb,
               __half* __restrict__ H, int symm) {
    int bx = blockIdx.x, by = blockIdx.y;
    if (symm && bx < by) return;

    extern __shared__ float smem[];
    int tid = threadIdx.x;
    int lane = tid & 31, w = tid >> 5;
    int wm = w >> 1, wn = w & 1;
    int g = lane >> 2, c = lane & 3;
    size_t rA = (size_t)by * 128;
    size_t rB = (size_t)bx * 128;

    float acc[2][8][4] = {};

    gemm_issue_stage(A, B, rA, rB, 0, smem, tid);
    gemm_issue_stage(A, B, rA, rB, 32, smem + 8192, tid);

    for (int s = 0; s < 16; s++) {
        asm volatile("cp.async.wait_group 1;\n" ::);
        __syncthreads();
        {
            const float* As = smem + (s & 1) * 8192;
            const float* Bs = As + 4096;
#pragma unroll
            for (int k8 = 0; k8 < 4; k8++) {
                int kb = k8 * 8;
                uint32_t a[2][4];
#pragma unroll
                for (int mt = 0; mt < 2; mt++) {
                    int mb = wm * 32 + mt * 16;
                    a[mt][0] = __float_as_uint(As[SWZ(mb + g,     kb + c)]);
                    a[mt][1] = __float_as_uint(As[SWZ(mb + 8 + g, kb + c)]);
                    a[mt][2] = __float_as_uint(As[SWZ(mb + g,     kb + 4 + c)]);
                    a[mt][3] = __float_as_uint(As[SWZ(mb + 8 + g, kb + 4 + c)]);
                }
#pragma unroll
                for (int nt = 0; nt < 8; nt++) {
                    int nb_ = wn * 64 + nt * 8;
                    uint32_t b0 = __float_as_uint(Bs[SWZ(nb_ + g, kb + c)]);
                    uint32_t b1 = __float_as_uint(Bs[SWZ(nb_ + g, kb + 4 + c)]);
                    MMA_TF32(acc[0][nt], a[0], b0, b1);
                    MMA_TF32(acc[1][nt], a[1], b0, b1);
                }
            }
        }
        __syncthreads();
        if (s + 2 < 16)
            gemm_issue_stage(A, B, rA, rB, (s + 2) * 32, smem + ((s & 1) * 8192), tid);
        else
            asm volatile("cp.async.commit_group;\n" ::);
    }

    asm volatile("cp.async.wait_group 0;\n" ::);
    __syncthreads();   // smem free for transpose staging

    if (!symm) {
#pragma unroll
        for (int mt = 0; mt < 2; mt++) {
            size_t m0 = rA + wm * 32 + mt * 16 + g;
            float na0 = __ldg(na + m0);
            float na1 = __ldg(na + m0 + 8);
#pragma unroll
            for (int nt = 0; nt < 8; nt++) {
                size_t n0 = rB + wn * 64 + nt * 8 + 2 * c;
                float nb0 = __ldg(nb + n0);
                float nb1 = __ldg(nb + n0 + 1);
                float2 o;
                o.x = sqrtf(fmaxf(na0 + nb0 - 2.0f * acc[mt][nt][0], 1e-12f));
                o.y = sqrtf(fmaxf(na0 + nb1 - 2.0f * acc[mt][nt][1], 1e-12f));
                *(__half2*)(H + m0 * NN + n0) = __float22half2_rn(o);
                o.x = sqrtf(fmaxf(na1 + nb0 - 2.0f * acc[mt][nt][2], 1e-12f));
                o.y = sqrtf(fmaxf(na1 + nb1 - 2.0f * acc[mt][nt][3], 1e-12f));
                *(__half2*)(H + (m0 + 8) * NN + n0) = __float22half2_rn(o);
            }
        }
        return;
    }

    // symmetric epilogue: direct writes + smem-transposed mirror (64 n-rows/half)
    for (int half = 0; half < 2; half++) {
        if (wn == half) {
#pragma unroll
            for (int mt = 0; mt < 2; mt++) {
                int ml0 = wm * 32 + mt * 16 + g;     // 0..127 local m
                size_t m0 = rA + ml0;
                float na0 = __ldg(na + m0);
                float na1 = __ldg(na + m0 + 8);
#pragma unroll
                for (int nt = 0; nt < 8; nt++) {
                    int nl = nt * 8 + 2 * c;         // 0..63 within half
                    size_t n0 = rB + half * 64 + nl;
                    float nb0 = __ldg(nb + n0);
                    float nb1 = __ldg(nb + n0 + 1);
                    float2 o;
                    o.x = sqrtf(fmaxf(na0 + nb0 - 2.0f * acc[mt][nt][0], 1e-12f));
                    o.y = sqrtf(fmaxf(na0 + nb1 - 2.0f * acc[mt][nt][1], 1e-12f));
                    *(__half2*)(H + m0 * NN + n0) = __float22half2_rn(o);
                    smem[nl * 132 + ml0]       = o.x;
                    smem[(nl + 1) * 132 + ml0] = o.y;
                    o.x = sqrtf(fmaxf(na1 + nb0 - 2.0f * acc[mt][nt][2], 1e-12f));
                    o.y = sqrtf(fmaxf(na1 + nb1 - 2.0f * acc[mt][nt][3], 1e-12f));
                    *(__half2*)(H + (m0 + 8) * NN + n0) = __float22half2_rn(o);
                    smem[nl * 132 + ml0 + 8]       = o.x;
                    smem[(nl + 1) * 132 + ml0 + 8] = o.y;
                }
            }
        }
        __syncthreads();
        if (bx != by) {
            for (int idx = tid; idx < 64 * 32; idx += 256) {
                int row = idx >> 5, c4 = (idx & 31) << 2;
                float4 v = *(const float4*)&smem[row * 132 + c4];
                size_t gr = rB + half * 64 + row;
                __half2 h0 = __float22half2_rn(make_float2(v.x, v.y));
                __half2 h1 = __float22half2_rn(make_float2(v.z, v.w));
                uint2 pk;
                pk.x = *(uint32_t*)&h0;
                pk.y = *(uint32_t*)&h1;
                *(uint2*)(H + gr * NN + rA + c4) = pk;
            }
        }
        __syncthreads();
    }
}

// fp32 diagonal fix (reduction order differs from sqnorm -> reference-like roundoff).
__global__ void __launch_bounds__(256)
diag_fix_kernel(const float* __restrict__ X, const float* __restrict__ n,
                __half* __restrict__ H) {
    int row = blockIdx.x * 8 + (threadIdx.x >> 5);
    int l = threadIdx.x & 31;
    const float* xr = X + (size_t)row * DD;
    float s = 0.0f;
#pragma unroll
    for (int k = 0; k < DD / 32; k++) {
        float v = xr[l + k * 32];
        s = fmaf(v, v, s);
    }
#pragma unroll
    for (int o = 16; o > 0; o >>= 1)
        s += __shfl_xor_sync(0xFFFFFFFFu, s, o);
    if (l == 0) {
        float d = sqrtf(fmaxf(2.0f * n[row] - 2.0f * s, 1e-12f));
        H[(size_t)row * NN + row] = __float2half_rn(d);
    }
}

// ---------------- lse kernels (fp16, branch-free, base-2) --------------------------

__global__ void __launch_bounds__(256) zero_kernel(float* __restrict__ p, int n) {
    int i = blockIdx.x * 256 + threadIdx.x;
    if (i < n) p[i] = 0.0f;
}

// Fused 3-matrix row-lse: grid (NN, 3). y=0: f from (Hzx, g); y=1: p from (Hzz, p);
// y=2: q from (Hxx, q). v served from L1 via __ldg, warp-shfl tail reduce.
__global__ void __launch_bounds__(256)
rowlse3_kernel(const __half* __restrict__ Hzx, const __half* __restrict__ Hzz,
               const __half* __restrict__ Hxx, const float* __restrict__ A,
               float* __restrict__ B, float cu, float cl) {
    int y = blockIdx.y;
    const __half* C = (y == 0) ? Hzx : (y == 1) ? Hzz : Hxx;
    const float* v  = A + ((y == 0) ? NN : (y == 1) ? 2 * NN : 3 * NN);
    const float* uo = (y == 0) ? A : v;
    float* uout     = B + ((y == 0) ? 0 : (y == 1) ? 2 * NN : 3 * NN);

    __shared__ float redm[8], reds[8];
    int tid = threadIdx.x;
    int lane = tid & 31, wid = tid >> 5;
    int row = blockIdx.x;

    const uint4* Crow = (const uint4*)(C + (size_t)row * NN);
    const float4* v4 = (const float4*)v;
    float a[32];
#pragma unroll
    for (int jj = 0; jj < 4; jj++) {
        int u = tid + jj * 256;
        uint4 raw = __ldcs(Crow + u);
        float4 v01 = __ldg(v4 + 2 * u);
        float4 v23 = __ldg(v4 + 2 * u + 1);
        const __half2* hp = (const __half2*)&raw;
        float2 c0 = __half22float2(hp[0]);
        float2 c1 = __half22float2(hp[1]);
        float2 c2 = __half22float2(hp[2]);
        float2 c3 = __half22float2(hp[3]);
        a[jj * 8 + 0] = (v01.x - c0.x) * K2F;
        a[jj * 8 + 1] = (v01.y - c0.y) * K2F;
        a[jj * 8 + 2] = (v01.z - c1.x) * K2F;
        a[jj * 8 + 3] = (v01.w - c1.y) * K2F;
        a[jj * 8 + 4] = (v23.x - c2.x) * K2F;
        a[jj * 8 + 5] = (v23.y - c2.y) * K2F;
        a[jj * 8 + 6] = (v23.z - c3.x) * K2F;
        a[jj * 8 + 7] = (v23.w - c3.y) * K2F;
    }
    float mx[16];
#pragma unroll
    for (int i = 0; i < 16; i++) mx[i] = fmaxf(a[i], a[i + 16]);
#pragma unroll
    for (int st = 8; st > 0; st >>= 1)
#pragma unroll
        for (int i = 0; i < 8; i++)
            if (i < st) mx[i] = fmaxf(mx[i], mx[i + st]);
    float m = mx[0];
    float s0 = 0.0f, s1 = 0.0f, s2 = 0.0f, s3 = 0.0f;
#pragma unroll
    for (int i = 0; i < 32; i += 4) {
        s0 += ex2(a[i]     - m);
        s1 += ex2(a[i + 1] - m);
        s2 += ex2(a[i + 2] - m);
        s3 += ex2(a[i + 3] - m);
    }
    float s = (s0 + s1) + (s2 + s3);

#pragma unroll
    for (int o = 16; o > 0; o >>= 1) {
        float m2 = __shfl_xor_sync(0xFFFFFFFFu, m, o);
        float sb = __shfl_xor_sync(0xFFFFFFFFu, s, o);
        float M = fmaxf(m, m2);
        s = s * ex2(m - M) + sb * ex2(m2 - M);
        m = M;
    }
    if (lane == 0) { redm[wid] = m; reds[wid] = s; }
    __syncthreads();
    if (tid == 0) {
        m = redm[0]; s = reds[0];
#pragma unroll
        for (int i = 1; i < 8; i++) {
            float m2 = redm[i], sb = reds[i];
            float M = fmaxf(m, m2);
            s = s * ex2(m - M) + sb * ex2(m2 - M);
            m = M;
        }
        uout[row] = cu * uo[row] + cl * ((m + lg2(s)) * LN2F + KLOG);
    }
}

// Column-lse pass 1: batched two-phase (16-row register batches; 1.125 ex2/elem).
// grid (16, 32): x = 256-half2 col tile, y = 256-row chunk.
__global__ void __launch_bounds__(256)
collse_part_h2_kernel(const __half* __restrict__ C, const float* __restrict__ v) {
    __shared__ float fs2[256];
    int tid = threadIdx.x;
    int col2 = blockIdx.x * 256 + tid;
    int r0 = blockIdx.y * 256;
    fs2[tid] = v[r0 + tid] * K2F;
    __syncthreads();
    const __half2* Cp = (const __half2*)C + (size_t)r0 * (NN / 2) + col2;
    float rm0 = -CUDART_INF_F, rs0 = 0.0f, rm1 = -CUDART_INF_F, rs1 = 0.0f;
#pragma unroll 1
    for (int b = 0; b < 16; b++) {
        float a0[16], a1[16];
#pragma unroll
        for (int r = 0; r < 16; r++) {
            float2 cf = __half22float2(__ldcs(Cp));
            Cp += NN / 2;
            float pv = fs2[b * 16 + r];
            a0[r] = fmaf(cf.x, -K2F, pv);
            a1[r] = fmaf(cf.y, -K2F, pv);
        }
        float t0[8], t1[8];
#pragma unroll
        for (int i = 0; i < 8; i++) {
            t0[i] = fmaxf(a0[i], a0[i + 8]);
            t1[i] = fmaxf(a1[i], a1[i + 8]);
        }
#pragma unroll
        for (int st = 4; st > 0; st >>= 1)
#pragma unroll
            for (int i = 0; i < 4; i++)
                if (i < st) {
                    t0[i] = fmaxf(t0[i], t0[i + st]);
                    t1[i] = fmaxf(t1[i], t1[i + st]);
                }
        float m0 = t0[0], m1 = t1[0];
        float sa0 = 0.0f, sb0 = 0.0f, sa1 = 0.0f, sb1 = 0.0f;
#pragma unroll
        for (int i = 0; i < 16; i += 2) {
            sa0 += ex2(a0[i]     - m0);
            sb0 += ex2(a0[i + 1] - m0);
            sa1 += ex2(a1[i]     - m1);
            sb1 += ex2(a1[i + 1] - m1);
        }
        float s0 = sa0 + sb0, s1 = sa1 + sb1;
        float M0 = fmaxf(rm0, m0);
        rs0 = rs0 * ex2(rm0 - M0) + s0 * ex2(m0 - M0);
        rm0 = M0;
        float M1 = fmaxf(rm1, m1);
        rs1 = rs1 * ex2(rm1 - M1) + s1 * ex2(m1 - M1);
        rm1 = M1;
    }
    size_t base = (size_t)blockIdx.y * NN + 2 * col2;
    *(float2*)&g_partM[base] = make_float2(rm0, rm1);
    *(float2*)&g_partS[base] = make_float2(rs0, rs1);
}

// Combine 32 partials per column (base-2) + apply update.
__global__ void __launch_bounds__(256)
collse_comb2_kernel(const float* __restrict__ uold, float* __restrict__ uout,
                    float cu, float cl) {
    int j = blockIdx.x * 256 + threadIdx.x;
    float m = -CUDART_INF_F, s = 0.0f;
#pragma unroll
    for (int rc = 0; rc < 32; rc++) {
        float m2 = g_partM[(size_t)rc * NN + j];
        float s2 = g_partS[(size_t)rc * NN + j];
        float M = fmaxf(m, m2);
        s = s * ex2(m - M) + s2 * ex2(m2 - M);
        m = M;
    }
    uout[j] = cu * uold[j] + cl * ((m + lg2(s)) * LN2F + KLOG);
}

__global__ void __launch_bounds__(256)
final_reduce_kernel(const float* __restrict__ fe, const float* __restrict__ pe,
                    const float* __restrict__ ge, const float* __restrict__ qe,
                    float* __restrict__ out) {
    __shared__ float sm[256];
    float s = 0.0f;
    for (int i = threadIdx.x; i < NN; i += 256)
        s += (fe[i] - pe[i]) + (ge[i] - qe[i]);
    sm[threadIdx.x] = s;
    __syncthreads();
    for (int o = 128; o > 0; o >>= 1) {
        if (threadIdx.x < o) sm[threadIdx.x] += sm[threadIdx.x + o];
        __syncthreads();
    }
    if (threadIdx.x == 0) out[0] = sm[0] * (1.0f / 8192.0f);
}

// ---------------- module preload at static-init -------------------------------
namespace {
struct ModulePreload {
    ModulePreload() {
        void* p = nullptr;
        cudaGetSymbolAddress(&p, g_Hzx);
        (void)p;
    }
};
ModulePreload g_module_preload_;
}  // namespace

// ---------------- launch ------------------------------------------------------
extern "C" void kernel_launch(void* const* d_in, const int* in_sizes, int n_in,
                              void* d_out, int out_size) {
    const float* X = (const float*)d_in[0];   // x        (xt)
    const float* Z = (const float*)d_in[1];   // prior_z  (xs)
    float* out = (float*)d_out;

    float *Zr, *Xr, *nz, *nx, *vb;
    __half *Hzx, *Hzz, *Hxx;
    cudaGetSymbolAddress((void**)&Hzx, g_Hzx);
    cudaGetSymbolAddress((void**)&Hzz, g_Hzz);
    cudaGetSymbolAddress((void**)&Hxx, g_Hxx);
    cudaGetSymbolAddress((void**)&Zr,  g_Zr);
    cudaGetSymbolAddress((void**)&Xr,  g_Xr);
    cudaGetSymbolAddress((void**)&nz,  g_nz);
    cudaGetSymbolAddress((void**)&nx,  g_nx);
    cudaGetSymbolAddress((void**)&vb,  g_vecbuf);

    cudaFuncSetAttribute(gemm_tc_kernel,
                         cudaFuncAttributeMaxDynamicSharedMemorySize, 65536);

    // --- setup: tf32 pre-round, fp32 norms, three fp16 distance matrices + diag fix ---
    preround_kernel<<<(NN * DD) / 256, 256>>>(Z, Zr);
    preround_kernel<<<(NN * DD) / 256, 256>>>(X, Xr);
    sqnorm_kernel<<<NN, 128>>>(Z, nz);
    sqnorm_kernel<<<NN, 128>>>(X, nx);
    dim3 gg(64, 64);
    gemm_tc_kernel<<<gg, 256, 65536>>>(Zr, Xr, nz, nx, Hzx, 0);
    gemm_tc_kernel<<<gg, 256, 65536>>>(Zr, Zr, nz, nz, Hzz, 1);
    gemm_tc_kernel<<<gg, 256, 65536>>>(Xr, Xr, nx, nx, Hxx, 1);
    diag_fix_kernel<<<NN / 8, 256>>>(Z, nz, Hzz);
    diag_fix_kernel<<<NN / 8, 256>>>(X, nx, Hxx);

    zero_kernel<<<(4 * NN) / 256, 256>>>(vb, 4 * NN);

    const float cu_it = 0.5f;
    const float cl_it = -0.5f * 0.05f;

    // --- 50 damped symmetric Sinkhorn iterations (3 kernels/iter) ---
    for (int it = 0; it < 50; ++it) {
        float* A = vb + (it & 1) * 4 * NN;
        float* B = vb + ((it & 1) ^ 1) * 4 * NN;
        rowlse3_kernel<<<dim3(NN, 3), 256>>>(Hzx, Hzz, Hxx, A, B, cu_it, cl_it);
        collse_part_h2_kernel<<<dim3(16, 32), 256>>>(Hzx, A);
        collse_comb2_kernel<<<32, 256>>>(A + NN, B + NN, cu_it, cl_it);
    }

    // --- extrapolation = one more half-iteration with (cu=0, cl=-eps) on fp16 costs ---
    {
        float* A = vb;             // final carry (f,g,p,q) in buffer 0
        float* E = vb + 4 * NN;    // f_e, g_e, p_e, q_e (reuse buffer 1)
        const float cu_e = 0.0f;
        const float cl_e = -0.05f;
        rowlse3_kernel<<<dim3(NN, 3), 256>>>(Hzx, Hzz, Hxx, A, E, cu_e, cl_e); // f_e, p_e, q_e
        collse_part_h2_kernel<<<dim3(16, 32), 256>>>(Hzx, A);
        collse_comb2_kernel<<<32, 256>>>(A + NN, E + NN, cu_e, cl_e);          // g_e
        final_reduce_kernel<<<1, 256>>>(E, E + 2 * NN, E + NN, E + 3 * NN, out);
    }
}